// round 3
// baseline (speedup 1.0000x reference)
#include <cuda_runtime.h>
#include <cuda_bf16.h>
#include <math.h>

// ---------------------------------------------------------------------------
// Problem constants
// ---------------------------------------------------------------------------
#define B_    16
#define N_    2048
#define NOTE_ 512
#define BH_   128     // BEAT_H
#define MH_   64      // MEAS_H
#define FH_   128     // FINAL_H
#define NB_   256     // NUM_BEATS
#define NM_   64      // NUM_MEAS
#define OUT_  11
#define D_    10      // OUT-1
#define GF_   512     // 4*FH == 4*BH
#define LDF_  715     // fin input width  (512+128+64+11)
#define LDT_  203     // tempo input width (128+64+1+10)

// ---------------------------------------------------------------------------
// Device scratch (static globals: allocation-free)
// ---------------------------------------------------------------------------
__device__ float g_Gnote[(size_t)B_ * N_ * GF_]; // note_emb @ Wih_f[:, :512]^T
__device__ float g_TBf[B_ * NB_ * GF_];          // beat_emb @ Wih_f[:, 512:640]^T
__device__ float g_TMf[B_ * NM_ * GF_];          // meas_emb @ Wih_f[:, 640:704]^T + bih_f + bhh_f
__device__ float g_TBt[B_ * NB_ * GF_];          // beat_emb @ Wih_t[:, :128]^T
__device__ float g_TMt[B_ * NM_ * GF_];          // meas_emb @ Wih_t[:, 128:192]^T + bih_t + bhh_t
__device__ float g_WfT[FH_ * GF_];               // Whh_f transposed: WT[k][gate]
__device__ float g_WtT[BH_ * GF_];               // Whh_t transposed: WT[k][gate]
__device__ unsigned char g_pad[B_ * N_];

// ---------------------------------------------------------------------------
// Helpers
// ---------------------------------------------------------------------------
__device__ __forceinline__ float warp_sum_f(float v) {
#pragma unroll
    for (int o = 16; o; o >>= 1) v += __shfl_xor_sync(0xffffffffu, v, o);
    return v;
}
__device__ __forceinline__ float warp_max_f(float v) {
#pragma unroll
    for (int o = 16; o; o >>= 1) v = fmaxf(v, __shfl_xor_sync(0xffffffffu, v, o));
    return v;
}
__device__ __forceinline__ float sigmoidf_(float x) {
    return 1.0f / (1.0f + expf(-x));
}

// ---------------------------------------------------------------------------
// Transpose Whh (512 x 128) -> WT (128 x 512)
// ---------------------------------------------------------------------------
__global__ void transpose_whh_kernel(const float* __restrict__ W, float* __restrict__ WT) {
    int idx = blockIdx.x * 256 + threadIdx.x;   // 65536 elements
    int g = idx >> 7;
    int k = idx & 127;
    WT[k * GF_ + g] = W[idx];
}

// ---------------------------------------------------------------------------
// pad[row] = (sum(note_emb[row, :]) == 0)
// ---------------------------------------------------------------------------
__global__ void pad_kernel(const float* __restrict__ note, unsigned char* __restrict__ pad) {
    int row = blockIdx.x;
    float s = 0.f;
    for (int k = threadIdx.x; k < NOTE_; k += 128) s += note[(size_t)row * NOTE_ + k];
    s = warp_sum_f(s);
    __shared__ float red[4];
    if ((threadIdx.x & 31) == 0) red[threadIdx.x >> 5] = s;
    __syncthreads();
    if (threadIdx.x == 0)
        pad[row] = ((red[0] + red[1] + red[2] + red[3]) == 0.0f) ? 1 : 0;
}

// ---------------------------------------------------------------------------
// GEMM: C[M x 512] = A[M x K] @ W(rows of length ldw, cols [cofs, cofs+K))^T
// BM=128, BN=64, BK=16, 256 threads, 8x4 microtile. M,K multiples of 128/16.
// ---------------------------------------------------------------------------
#define GBM 128
#define GBN 64
#define GBK 16

__global__ void __launch_bounds__(256) gemm_nt_kernel(
    const float* __restrict__ A, int lda, int K,
    const float* __restrict__ W, int ldw, int cofs,
    float* __restrict__ C,
    const float* __restrict__ bias0, const float* __restrict__ bias1)
{
    __shared__ __align__(16) float As[GBK][GBM + 4];  // row stride 132*4=528=33*16B
    __shared__ __align__(16) float Bs[GBK][GBN];

    const int m0 = blockIdx.x * GBM;
    const int n0 = blockIdx.y * GBN;
    const int t  = threadIdx.x;
    const int tx = t & 15;      // n dir: 16 * 4 = 64
    const int ty = t >> 4;      // m dir: 16 * 8 = 128

    float acc[8][4];
#pragma unroll
    for (int r = 0; r < 8; r++)
#pragma unroll
        for (int c = 0; c < 4; c++) acc[r][c] = 0.f;

    for (int k0 = 0; k0 < K; k0 += GBK) {
        __syncthreads();
        // A tile: 128x16 = 512 float4 loads
#pragma unroll
        for (int rr = 0; rr < 2; rr++) {
            int f = t + rr * 256;
            int row = f >> 2;
            int c4 = f & 3;
            float4 av = *(const float4*)(A + (size_t)(m0 + row) * lda + k0 + c4 * 4);
            As[c4 * 4 + 0][row] = av.x;
            As[c4 * 4 + 1][row] = av.y;
            As[c4 * 4 + 2][row] = av.z;
            As[c4 * 4 + 3][row] = av.w;
        }
        // B tile: 16x64 scalars (ldw may be odd)
#pragma unroll
        for (int rr = 0; rr < 4; rr++) {
            int f = t + rr * 256;
            int kk = f & 15;
            int n = f >> 4;
            Bs[kk][n] = W[(size_t)(n0 + n) * ldw + cofs + k0 + kk];
        }
        __syncthreads();
#pragma unroll
        for (int kk = 0; kk < GBK; kk++) {
            float4 a0 = *(const float4*)&As[kk][ty * 8];
            float4 a1 = *(const float4*)&As[kk][ty * 8 + 4];
            float4 bv = *(const float4*)&Bs[kk][tx * 4];
            float av[8] = {a0.x, a0.y, a0.z, a0.w, a1.x, a1.y, a1.z, a1.w};
            float bb[4] = {bv.x, bv.y, bv.z, bv.w};
#pragma unroll
            for (int r = 0; r < 8; r++)
#pragma unroll
                for (int c = 0; c < 4; c++) acc[r][c] += av[r] * bb[c];
        }
    }

    const int gbase = n0 + tx * 4;
#pragma unroll
    for (int r = 0; r < 8; r++) {
        int m = m0 + ty * 8 + r;
        float4 v = make_float4(acc[r][0], acc[r][1], acc[r][2], acc[r][3]);
        if (bias0) {
            v.x += bias0[gbase + 0] + bias1[gbase + 0];
            v.y += bias0[gbase + 1] + bias1[gbase + 1];
            v.z += bias0[gbase + 2] + bias1[gbase + 2];
            v.w += bias0[gbase + 3] + bias1[gbase + 3];
        }
        *(float4*)&C[(size_t)m * GF_ + gbase] = v;
    }
}

// ---------------------------------------------------------------------------
// Persistent scan kernel: one block per batch, 512 threads, 2048 steps
// ---------------------------------------------------------------------------
struct __align__(16) ScanSmem {
    float hist[N_ * D_];        // unmasked output history cols 1..10 (80 KB)
    float Wtf[GF_ * 11];        // Wih_f[:, 704:715]
    float Wtt[GF_ * 11];        // Wih_t[:, 192:203]
    float Wfc[D_ * FH_];        // W_fc
    float Wtfc[BH_];            // W_tfc
    float part[4 * GF_];        // k-split partials
    float g[GF_];               // gate preactivations
    float hf[FH_], cf[FH_], ht[BH_], ct[BH_];
    float prev[16];             // prev_out (11 used)
    float beat_res[16];         // current beat attention result (10 used)
    float va[16];               // Wa^T @ ctx
    float bfc[16];              // b_fc
    float c0;                   // ba @ ctx
    float btfc;                 // b_tfc
    int   beats[N_];
    int   meas[N_];
};

__global__ void __launch_bounds__(512, 1) scan_kernel(
    const int* __restrict__ beat_numbers, const int* __restrict__ measure_numbers,
    const float* __restrict__ Wa, const float* __restrict__ ba, const float* __restrict__ ctx,
    const float* __restrict__ Wih_t, const float* __restrict__ Wih_f,
    const float* __restrict__ W_fc, const float* __restrict__ b_fc,
    const float* __restrict__ W_tfc, const float* __restrict__ b_tfc,
    float* __restrict__ out)
{
    extern __shared__ char smem_raw[];
    ScanSmem& s = *reinterpret_cast<ScanSmem*>(smem_raw);

    const int b    = blockIdx.x;
    const int t    = threadIdx.x;
    const int lane = t & 31;
    const int wid  = t >> 5;
    const int qg4  = t & 127;   // float4 gate index (gates 4*qg4 .. 4*qg4+3)
    const int kh   = t >> 7;    // k quarter: [32*kh, 32*kh+32)

    // ---- init shared state ----
    for (int idx = t; idx < GF_ * 11; idx += 512) {
        int gg = idx / 11, j = idx - gg * 11;
        s.Wtf[idx] = Wih_f[(size_t)gg * LDF_ + 704 + j];
        s.Wtt[idx] = Wih_t[(size_t)gg * LDT_ + 192 + j];
    }
    for (int idx = t; idx < D_ * FH_; idx += 512) s.Wfc[idx] = W_fc[idx];
    if (t < BH_) s.Wtfc[t] = W_tfc[t];
    if (t < D_)  s.bfc[t] = b_fc[t];
    if (t < 16)  { s.prev[t] = 0.f; s.beat_res[t] = 0.f; }
    if (t < FH_) { s.hf[t] = 0.f; s.cf[t] = 0.f; s.ht[t] = 0.f; s.ct[t] = 0.f; }
    if (t < D_) {
        float v = 0.f;
#pragma unroll
        for (int k = 0; k < D_; k++) v += ctx[k] * Wa[k * D_ + t];
        s.va[t] = v;
    }
    if (t == 0) {
        float v = 0.f;
#pragma unroll
        for (int k = 0; k < D_; k++) v += ba[k] * ctx[k];
        s.c0 = v;
        s.btfc = b_tfc[0];
    }
    for (int i = t; i < N_; i += 512) {
        s.beats[i] = beat_numbers[b * N_ + i];
        s.meas[i]  = measure_numbers[b * N_ + i];
    }
    __syncthreads();

    const int beat0 = s.beats[0];
    const int meas0 = s.meas[0];
    int rs = 0;  // start index of the current beat run (uniform across block)

    for (int i = 0; i < N_; ++i) {
        const int bi = s.beats[i];
        const bool changed = (i == 0) || (bi != s.beats[i - 1]);
        const int cb = bi - beat0;
        const int cm = s.meas[i] - meas0;

        // Early prefetch of per-step precomputed rows (independent of recurrence)
        const float* Gn   = g_Gnote + ((size_t)b * N_ + i) * GF_;
        const float* TBfr = g_TBf + ((size_t)b * NB_ + cb) * GF_;
        const float* TMfr = g_TMf + ((size_t)b * NM_ + cm) * GF_;
        const float gn_v  = Gn[t];
        const float tbf_v = TBfr[t];
        const float tmf_v = TMfr[t];
        const bool  pd    = (g_pad[b * N_ + i] != 0);

        if (changed) {
            // ---- attention over previous beat run [rs, i) (warp 0) ----
            if (i > 0) {
                if (wid == 0) {
                    float mx = -1e30f;
                    for (int n = rs + lane; n < i; n += 32) {
                        const float* hrow = &s.hist[n * D_];
                        float sim = s.c0;
#pragma unroll
                        for (int j = 0; j < D_; j++) sim += hrow[j] * s.va[j];
                        mx = fmaxf(mx, sim);
                    }
                    mx = warp_max_f(mx);
                    float ssum = 0.f;
                    float acc[D_];
#pragma unroll
                    for (int j = 0; j < D_; j++) acc[j] = 0.f;
                    for (int n = rs + lane; n < i; n += 32) {
                        const float* hrow = &s.hist[n * D_];
                        float sim = s.c0;
#pragma unroll
                        for (int j = 0; j < D_; j++) sim += hrow[j] * s.va[j];
                        float e = expf(sim - mx);
                        ssum += e;
#pragma unroll
                        for (int j = 0; j < D_; j++) acc[j] += e * hrow[j];
                    }
                    ssum = warp_sum_f(ssum);
#pragma unroll
                    for (int j = 0; j < D_; j++) acc[j] = warp_sum_f(acc[j]);
                    if (lane == 0) {
                        float inv = 1.0f / ssum;
#pragma unroll
                        for (int j = 0; j < D_; j++) s.beat_res[j] = acc[j] * inv;
                    }
                }
            }
            __syncthreads();  // beat_res visible

            // ---- tempo LSTM gates (quad k-split over Whh_t^T) ----
            {
                const float4* W4 = reinterpret_cast<const float4*>(g_WtT)
                                 + (size_t)kh * 32 * (GF_ / 4) + qg4;
                float4 a = make_float4(0.f, 0.f, 0.f, 0.f);
#pragma unroll 8
                for (int k0 = 0; k0 < 32; ++k0) {
                    float4 w = W4[(size_t)k0 * (GF_ / 4)];
                    float h = s.ht[kh * 32 + k0];
                    a.x += h * w.x; a.y += h * w.y; a.z += h * w.z; a.w += h * w.w;
                }
                reinterpret_cast<float4*>(s.part)[kh * (GF_ / 4) + qg4] = a;
            }
            __syncthreads();
            {
                const float* TBtr = g_TBt + ((size_t)b * NB_ + cb) * GF_;
                const float* TMtr = g_TMt + ((size_t)b * NM_ + cm) * GF_;
                float acc = s.part[t] + s.part[GF_ + t] + s.part[2 * GF_ + t] + s.part[3 * GF_ + t]
                          + TBtr[t] + TMtr[t];
                const float* wr = &s.Wtt[t * 11];
                acc += s.prev[0] * wr[0];
#pragma unroll
                for (int j = 0; j < D_; j++) acc += s.beat_res[j] * wr[1 + j];
                s.g[t] = acc;
            }
            __syncthreads();
            if (t < BH_) {
                float c2 = sigmoidf_(s.g[BH_ + t]) * s.ct[t]
                         + sigmoidf_(s.g[t]) * tanhf(s.g[2 * BH_ + t]);
                float h2 = sigmoidf_(s.g[3 * BH_ + t]) * tanhf(c2);
                s.ct[t] = c2;
                s.ht[t] = h2;
            }
            __syncthreads();
            if (wid == 0) {
                float p = s.ht[lane]      * s.Wtfc[lane]
                        + s.ht[lane + 32] * s.Wtfc[lane + 32]
                        + s.ht[lane + 64] * s.Wtfc[lane + 64]
                        + s.ht[lane + 96] * s.Wtfc[lane + 96];
                p = warp_sum_f(p);
                if (lane == 0) s.prev[0] = p + s.btfc;
            }
            __syncthreads();
            rs = i;  // new run starts here
        }

        // ---- final LSTM gates (quad k-split over Whh_f^T) ----
        {
            const float4* W4 = reinterpret_cast<const float4*>(g_WfT)
                             + (size_t)kh * 32 * (GF_ / 4) + qg4;
            float4 a = make_float4(0.f, 0.f, 0.f, 0.f);
#pragma unroll 8
            for (int k0 = 0; k0 < 32; ++k0) {
                float4 w = W4[(size_t)k0 * (GF_ / 4)];
                float h = s.hf[kh * 32 + k0];
                a.x += h * w.x; a.y += h * w.y; a.z += h * w.z; a.w += h * w.w;
            }
            reinterpret_cast<float4*>(s.part)[kh * (GF_ / 4) + qg4] = a;
        }
        __syncthreads();
        {
            float acc = s.part[t] + s.part[GF_ + t] + s.part[2 * GF_ + t] + s.part[3 * GF_ + t]
                      + gn_v + tbf_v + tmf_v;
            const float* wr = &s.Wtf[t * 11];
#pragma unroll
            for (int j = 0; j < OUT_; j++) acc += s.prev[j] * wr[j];
            s.g[t] = acc;
        }
        __syncthreads();
        if (t < FH_) {
            float c2 = sigmoidf_(s.g[FH_ + t]) * s.cf[t]
                     + sigmoidf_(s.g[t]) * tanhf(s.g[2 * FH_ + t]);
            float h2 = sigmoidf_(s.g[3 * FH_ + t]) * tanhf(c2);
            s.cf[t] = c2;
            s.hf[t] = h2;
        }
        __syncthreads();

        // ---- output fc + history + global write ----
        float* orow = out + ((size_t)b * N_ + i) * OUT_;
        if (wid < D_) {
            float p = s.hf[lane]      * s.Wfc[wid * FH_ + lane]
                    + s.hf[lane + 32] * s.Wfc[wid * FH_ + lane + 32]
                    + s.hf[lane + 64] * s.Wfc[wid * FH_ + lane + 64]
                    + s.hf[lane + 96] * s.Wfc[wid * FH_ + lane + 96];
            p = warp_sum_f(p);
            if (lane == 0) {
                float o = p + s.bfc[wid];
                s.prev[1 + wid] = o;
                s.hist[i * D_ + wid] = o;        // unmasked history for attention
                orow[1 + wid] = pd ? 0.f : o;
            }
        } else if (t == 320) {
            orow[0] = pd ? 0.f : s.prev[0];
        }
        __syncthreads();
    }
}

// ---------------------------------------------------------------------------
// Launch
// ---------------------------------------------------------------------------
extern "C" void kernel_launch(void* const* d_in, const int* in_sizes, int n_in,
                              void* d_out, int out_size) {
    const float* note_emb        = (const float*)d_in[0];
    const float* beat_emb        = (const float*)d_in[1];
    const float* measure_emb     = (const float*)d_in[2];
    const int*   beat_numbers    = (const int*)d_in[3];
    const int*   measure_numbers = (const int*)d_in[4];
    const float* Wa    = (const float*)d_in[5];
    const float* ba    = (const float*)d_in[6];
    const float* ctx   = (const float*)d_in[7];
    const float* Wih_t = (const float*)d_in[8];
    const float* Whh_t = (const float*)d_in[9];
    const float* bih_t = (const float*)d_in[10];
    const float* bhh_t = (const float*)d_in[11];
    const float* Wih_f = (const float*)d_in[12];
    const float* Whh_f = (const float*)d_in[13];
    const float* bih_f = (const float*)d_in[14];
    const float* bhh_f = (const float*)d_in[15];
    const float* W_fc  = (const float*)d_in[16];
    const float* b_fc  = (const float*)d_in[17];
    const float* W_tfc = (const float*)d_in[18];
    const float* b_tfc = (const float*)d_in[19];
    float* out = (float*)d_out;

    float *pG, *pTBf, *pTMf, *pTBt, *pTMt, *pWfT, *pWtT;
    unsigned char* pPad;
    cudaGetSymbolAddress((void**)&pG,   g_Gnote);
    cudaGetSymbolAddress((void**)&pTBf, g_TBf);
    cudaGetSymbolAddress((void**)&pTMf, g_TMf);
    cudaGetSymbolAddress((void**)&pTBt, g_TBt);
    cudaGetSymbolAddress((void**)&pTMt, g_TMt);
    cudaGetSymbolAddress((void**)&pWfT, g_WfT);
    cudaGetSymbolAddress((void**)&pWtT, g_WtT);
    cudaGetSymbolAddress((void**)&pPad, g_pad);

    cudaFuncSetAttribute(scan_kernel, cudaFuncAttributeMaxDynamicSharedMemorySize,
                         (int)sizeof(ScanSmem));

    transpose_whh_kernel<<<256, 256>>>(Whh_f, pWfT);
    transpose_whh_kernel<<<256, 256>>>(Whh_t, pWtT);
    pad_kernel<<<B_ * N_, 128>>>(note_emb, pPad);

    // G_note = note_emb @ Wih_f[:, 0:512]^T          (32768 x 512 x 512)
    gemm_nt_kernel<<<dim3((B_ * N_) / GBM, GF_ / GBN), 256>>>(
        note_emb, NOTE_, NOTE_, Wih_f, LDF_, 0, pG, nullptr, nullptr);
    // TBf = beat_emb @ Wih_f[:, 512:640]^T           (4096 x 128)
    gemm_nt_kernel<<<dim3((B_ * NB_) / GBM, GF_ / GBN), 256>>>(
        beat_emb, BH_, BH_, Wih_f, LDF_, NOTE_, pTBf, nullptr, nullptr);
    // TMf = measure_emb @ Wih_f[:, 640:704]^T + bih_f + bhh_f   (1024 x 64)
    gemm_nt_kernel<<<dim3((B_ * NM_) / GBM, GF_ / GBN), 256>>>(
        measure_emb, MH_, MH_, Wih_f, LDF_, NOTE_ + BH_, pTMf, bih_f, bhh_f);
    // TBt = beat_emb @ Wih_t[:, 0:128]^T
    gemm_nt_kernel<<<dim3((B_ * NB_) / GBM, GF_ / GBN), 256>>>(
        beat_emb, BH_, BH_, Wih_t, LDT_, 0, pTBt, nullptr, nullptr);
    // TMt = measure_emb @ Wih_t[:, 128:192]^T + bih_t + bhh_t
    gemm_nt_kernel<<<dim3((B_ * NM_) / GBM, GF_ / GBN), 256>>>(
        measure_emb, MH_, MH_, Wih_t, LDT_, BH_, pTMt, bih_t, bhh_t);

    scan_kernel<<<B_, 512, sizeof(ScanSmem)>>>(
        beat_numbers, measure_numbers, Wa, ba, ctx,
        Wih_t, Wih_f, W_fc, b_fc, W_tfc, b_tfc, out);

    (void)in_sizes; (void)n_in; (void)out_size;
}

// round 4
// speedup vs baseline: 1.6526x; 1.6526x over previous
#include <cuda_runtime.h>
#include <cuda_bf16.h>
#include <math.h>

// ---------------------------------------------------------------------------
// Problem constants
// ---------------------------------------------------------------------------
#define B_    16
#define N_    2048
#define NOTE_ 512
#define BH_   128     // BEAT_H
#define MH_   64      // MEAS_H
#define FH_   128     // FINAL_H
#define NB_   256     // NUM_BEATS
#define NM_   64      // NUM_MEAS
#define OUT_  11
#define D_    10      // OUT-1
#define GF_   512     // 4*FH == 4*BH
#define LDF_  715     // fin input width  (512+128+64+11)
#define LDT_  203     // tempo input width (128+64+1+10)
#define HR_   512     // history ring size (max beat-run << 512)

// ---------------------------------------------------------------------------
// Device scratch (static globals: allocation-free)
// ---------------------------------------------------------------------------
__device__ float g_Gnote[(size_t)B_ * N_ * GF_]; // note_emb @ Wih_f[:, :512]^T
__device__ float g_TBf[B_ * NB_ * GF_];          // beat_emb @ Wih_f[:, 512:640]^T
__device__ float g_TMf[B_ * NM_ * GF_];          // meas_emb @ Wih_f[:, 640:704]^T + biases
__device__ float g_TBt[B_ * NB_ * GF_];          // beat_emb @ Wih_t[:, :128]^T
__device__ float g_TMt[B_ * NM_ * GF_];          // meas_emb @ Wih_t[:, 128:192]^T + biases
__device__ float g_WfT[FH_ * GF_];               // Whh_f transposed: WT[k][gate]
__device__ float g_WtT[BH_ * GF_];               // Whh_t transposed: WT[k][gate]
__device__ unsigned char g_pad[B_ * N_];

// ---------------------------------------------------------------------------
// Helpers
// ---------------------------------------------------------------------------
__device__ __forceinline__ float warp_sum_f(float v) {
#pragma unroll
    for (int o = 16; o; o >>= 1) v += __shfl_xor_sync(0xffffffffu, v, o);
    return v;
}
__device__ __forceinline__ float warp_max_f(float v) {
#pragma unroll
    for (int o = 16; o; o >>= 1) v = fmaxf(v, __shfl_xor_sync(0xffffffffu, v, o));
    return v;
}
__device__ __forceinline__ float sigmoidf_(float x) {
    return 1.0f / (1.0f + expf(-x));
}
// packed fp32x2 FMA (sm_100+): d = a*b + d on two lanes at once
__device__ __forceinline__ void ffma2(unsigned long long& d, unsigned long long a,
                                      unsigned long long b) {
    asm("fma.rn.f32x2 %0, %1, %2, %0;" : "+l"(d) : "l"(a), "l"(b));
}
__device__ __forceinline__ unsigned long long packf2(float h) {
    unsigned long long r;
    unsigned int u = __float_as_uint(h);
    asm("mov.b64 %0, {%1, %1};" : "=l"(r) : "r"(u));
    return r;
}
__device__ __forceinline__ void unpackf2(unsigned long long v, float& lo, float& hi) {
    asm("mov.b64 {%0, %1}, %2;" : "=f"(lo), "=f"(hi) : "l"(v));
}

// ---------------------------------------------------------------------------
// Transpose Whh (512 x 128) -> WT (128 x 512)
// ---------------------------------------------------------------------------
__global__ void transpose_whh_kernel(const float* __restrict__ W, float* __restrict__ WT) {
    int idx = blockIdx.x * 256 + threadIdx.x;   // 65536 elements
    int g = idx >> 7;
    int k = idx & 127;
    WT[k * GF_ + g] = W[idx];
}

// ---------------------------------------------------------------------------
// pad[row] = (sum(note_emb[row, :]) == 0)
// ---------------------------------------------------------------------------
__global__ void pad_kernel(const float* __restrict__ note, unsigned char* __restrict__ pad) {
    int row = blockIdx.x;
    float s = 0.f;
    for (int k = threadIdx.x; k < NOTE_; k += 128) s += note[(size_t)row * NOTE_ + k];
    s = warp_sum_f(s);
    __shared__ float red[4];
    if ((threadIdx.x & 31) == 0) red[threadIdx.x >> 5] = s;
    __syncthreads();
    if (threadIdx.x == 0)
        pad[row] = ((red[0] + red[1] + red[2] + red[3]) == 0.0f) ? 1 : 0;
}

// ---------------------------------------------------------------------------
// GEMM: C[M x 512] = A[M x K] @ W(rows of length ldw, cols [cofs, cofs+K))^T
// BM=128, BN=64, BK=16, 256 threads, 8x4 microtile, double-buffered smem.
// ---------------------------------------------------------------------------
#define GBM 128
#define GBN 64
#define GBK 16

__global__ void __launch_bounds__(256) gemm_nt_kernel(
    const float* __restrict__ A, int lda, int K,
    const float* __restrict__ W, int ldw, int cofs,
    float* __restrict__ C,
    const float* __restrict__ bias0, const float* __restrict__ bias1)
{
    __shared__ __align__(16) float As[2][GBK][GBM + 4];
    __shared__ __align__(16) float Bs[2][GBK][GBN];

    const int m0 = blockIdx.x * GBM;
    const int n0 = blockIdx.y * GBN;
    const int t  = threadIdx.x;
    const int tx = t & 15;      // n dir: 16 * 4 = 64
    const int ty = t >> 4;      // m dir: 16 * 8 = 128

    // A-load indexing (persistent across tiles)
    const int a_row = t >> 2;        // with +256 twin
    const int a_c4  = t & 3;
    float acc[8][4];
#pragma unroll
    for (int r = 0; r < 8; r++)
#pragma unroll
        for (int c = 0; c < 4; c++) acc[r][c] = 0.f;

    const int nk = K / GBK;

    // preload tile 0 into buffer 0
    {
#pragma unroll
        for (int rr = 0; rr < 2; rr++) {
            int row = a_row + rr * 64;
            float4 av = *(const float4*)(A + (size_t)(m0 + row) * lda + a_c4 * 4);
            As[0][a_c4 * 4 + 0][row] = av.x;
            As[0][a_c4 * 4 + 1][row] = av.y;
            As[0][a_c4 * 4 + 2][row] = av.z;
            As[0][a_c4 * 4 + 3][row] = av.w;
        }
#pragma unroll
        for (int rr = 0; rr < 4; rr++) {
            int f = t + rr * 256;
            int kk = f & 15;
            int n = f >> 4;
            Bs[0][kk][n] = W[(size_t)(n0 + n) * ldw + cofs + kk];
        }
    }
    __syncthreads();

    for (int kt = 0; kt < nk; ++kt) {
        const int cur = kt & 1;
        const int nxt = cur ^ 1;
        if (kt + 1 < nk) {
            const int k0 = (kt + 1) * GBK;
#pragma unroll
            for (int rr = 0; rr < 2; rr++) {
                int row = a_row + rr * 64;
                float4 av = *(const float4*)(A + (size_t)(m0 + row) * lda + k0 + a_c4 * 4);
                As[nxt][a_c4 * 4 + 0][row] = av.x;
                As[nxt][a_c4 * 4 + 1][row] = av.y;
                As[nxt][a_c4 * 4 + 2][row] = av.z;
                As[nxt][a_c4 * 4 + 3][row] = av.w;
            }
#pragma unroll
            for (int rr = 0; rr < 4; rr++) {
                int f = t + rr * 256;
                int kk = f & 15;
                int n = f >> 4;
                Bs[nxt][kk][n] = W[(size_t)(n0 + n) * ldw + cofs + k0 + kk];
            }
        }
#pragma unroll
        for (int kk = 0; kk < GBK; kk++) {
            float4 a0 = *(const float4*)&As[cur][kk][ty * 8];
            float4 a1 = *(const float4*)&As[cur][kk][ty * 8 + 4];
            float4 bv = *(const float4*)&Bs[cur][kk][tx * 4];
            float av[8] = {a0.x, a0.y, a0.z, a0.w, a1.x, a1.y, a1.z, a1.w};
            float bb[4] = {bv.x, bv.y, bv.z, bv.w};
#pragma unroll
            for (int r = 0; r < 8; r++)
#pragma unroll
                for (int c = 0; c < 4; c++) acc[r][c] += av[r] * bb[c];
        }
        __syncthreads();
    }

    const int gbase = n0 + tx * 4;
#pragma unroll
    for (int r = 0; r < 8; r++) {
        int m = m0 + ty * 8 + r;
        float4 v = make_float4(acc[r][0], acc[r][1], acc[r][2], acc[r][3]);
        if (bias0) {
            v.x += bias0[gbase + 0] + bias1[gbase + 0];
            v.y += bias0[gbase + 1] + bias1[gbase + 1];
            v.z += bias0[gbase + 2] + bias1[gbase + 2];
            v.w += bias0[gbase + 3] + bias1[gbase + 3];
        }
        *(float4*)&C[(size_t)m * GF_ + gbase] = v;
    }
}

// ---------------------------------------------------------------------------
// Persistent scan kernel: one block per batch, 512 threads, 2048 steps.
// Whh_f^T rows [0,64) live in SMEM (128 KB); rows [64,128) stream from L2/L1.
// ---------------------------------------------------------------------------
struct __align__(16) ScanSmem {
    float wsm[64 * GF_];        // Whh_f^T rows k=0..63  (128 KB)
    float hist[HR_ * D_];       // unmasked output-history ring (20 KB)
    float Wtf[GF_ * 11];        // Wih_f[:, 704:715]
    float Wtt[GF_ * 11];        // Wih_t[:, 192:203]
    float Wfc[D_ * FH_];        // W_fc
    float part[4 * GF_];        // k-split partials
    float g[GF_];               // gate preactivations
    float Wtfc[BH_];            // W_tfc
    float hf[FH_], cf[FH_], ht[BH_], ct[BH_];
    float prev[16];             // prev_out (11 used)
    float beat_res[16];         // current beat attention result (10 used)
    float va[16];               // Wa^T @ ctx
    float bfc[16];              // b_fc
    float c0;                   // ba @ ctx
    float btfc;                 // b_tfc
    unsigned char cbA[N_];      // beat index (rel) per step
    unsigned char cmA[N_];      // measure index (rel) per step
    unsigned char chA[N_];      // changed flag per step
};

__global__ void __launch_bounds__(512, 1) scan_kernel(
    const int* __restrict__ beat_numbers, const int* __restrict__ measure_numbers,
    const float* __restrict__ Wa, const float* __restrict__ ba, const float* __restrict__ ctx,
    const float* __restrict__ Wih_t, const float* __restrict__ Wih_f,
    const float* __restrict__ W_fc, const float* __restrict__ b_fc,
    const float* __restrict__ W_tfc, const float* __restrict__ b_tfc,
    float* __restrict__ out)
{
    extern __shared__ char smem_raw[];
    ScanSmem& s = *reinterpret_cast<ScanSmem*>(smem_raw);

    const int b    = blockIdx.x;
    const int t    = threadIdx.x;
    const int lane = t & 31;
    const int wid  = t >> 5;
    const int qg4  = t & 127;   // float4 gate-quad index (gates 4*qg4 .. 4*qg4+3)
    const int kh   = t >> 7;    // k quarter: [32*kh, 32*kh+32)

    // ---- init shared state ----
    // weights rows 0..63 into smem (float4 copies)
    {
        const float4* src = reinterpret_cast<const float4*>(g_WfT);
        float4* dst = reinterpret_cast<float4*>(s.wsm);
        for (int idx = t; idx < 64 * GF_ / 4; idx += 512) dst[idx] = src[idx];
    }
    for (int idx = t; idx < GF_ * 11; idx += 512) {
        int gg = idx / 11, j = idx - gg * 11;
        s.Wtf[idx] = Wih_f[(size_t)gg * LDF_ + 704 + j];
        s.Wtt[idx] = Wih_t[(size_t)gg * LDT_ + 192 + j];
    }
    for (int idx = t; idx < D_ * FH_; idx += 512) s.Wfc[idx] = W_fc[idx];
    if (t < BH_) s.Wtfc[t] = W_tfc[t];
    if (t < D_)  s.bfc[t] = b_fc[t];
    if (t < 16)  { s.prev[t] = 0.f; s.beat_res[t] = 0.f; }
    if (t < FH_) { s.hf[t] = 0.f; s.cf[t] = 0.f; s.ht[t] = 0.f; s.ct[t] = 0.f; }
    if (t < D_) {
        float v = 0.f;
#pragma unroll
        for (int k = 0; k < D_; k++) v += ctx[k] * Wa[k * D_ + t];
        s.va[t] = v;
    }
    if (t == 0) {
        float v = 0.f;
#pragma unroll
        for (int k = 0; k < D_; k++) v += ba[k] * ctx[k];
        s.c0 = v;
        s.btfc = b_tfc[0];
    }
    {
        const int beat0 = beat_numbers[b * N_];
        const int meas0 = measure_numbers[b * N_];
        for (int i = t; i < N_; i += 512) {
            int bi = beat_numbers[b * N_ + i];
            int mi = measure_numbers[b * N_ + i];
            s.cbA[i] = (unsigned char)(bi - beat0);
            s.cmA[i] = (unsigned char)(mi - meas0);
            s.chA[i] = (i == 0) ? 1 : ((bi != beat_numbers[b * N_ + i - 1]) ? 1 : 0);
        }
    }
    __syncthreads();

    int rs = 0;  // start index of the current beat run (uniform across block)

    for (int i = 0; i < N_; ++i) {
        const bool changed = (s.chA[i] != 0);
        const int cb = s.cbA[i];
        const int cm = s.cmA[i];

        // Early prefetch of per-step precomputed rows (independent of recurrence)
        const float gn_v  = g_Gnote[((size_t)b * N_ + i) * GF_ + t];
        const float tbf_v = g_TBf[((size_t)b * NB_ + cb) * GF_ + t];
        const float tmf_v = g_TMf[((size_t)b * NM_ + cm) * GF_ + t];
        const bool  pd    = (g_pad[b * N_ + i] != 0);

        if (changed) {
            // ---- attention over previous beat run [rs, i) (warp 0) ----
            if (i > 0) {
                if (wid == 0) {
                    float mx = -1e30f;
                    for (int n = rs + lane; n < i; n += 32) {
                        const float* hrow = &s.hist[(n & (HR_ - 1)) * D_];
                        float sim = s.c0;
#pragma unroll
                        for (int j = 0; j < D_; j++) sim += hrow[j] * s.va[j];
                        mx = fmaxf(mx, sim);
                    }
                    mx = warp_max_f(mx);
                    float ssum = 0.f;
                    float acc[D_];
#pragma unroll
                    for (int j = 0; j < D_; j++) acc[j] = 0.f;
                    for (int n = rs + lane; n < i; n += 32) {
                        const float* hrow = &s.hist[(n & (HR_ - 1)) * D_];
                        float sim = s.c0;
#pragma unroll
                        for (int j = 0; j < D_; j++) sim += hrow[j] * s.va[j];
                        float e = expf(sim - mx);
                        ssum += e;
#pragma unroll
                        for (int j = 0; j < D_; j++) acc[j] += e * hrow[j];
                    }
                    ssum = warp_sum_f(ssum);
#pragma unroll
                    for (int j = 0; j < D_; j++) acc[j] = warp_sum_f(acc[j]);
                    if (lane == 0) {
                        float inv = 1.0f / ssum;
#pragma unroll
                        for (int j = 0; j < D_; j++) s.beat_res[j] = acc[j] * inv;
                    }
                }
            }
            __syncthreads();  // beat_res visible

            // ---- tempo LSTM gates (quad k-split over Whh_t^T, global) ----
            {
                const ulonglong2* W4 = reinterpret_cast<const ulonglong2*>(g_WtT)
                                     + (size_t)kh * 32 * (GF_ / 4) + qg4;
                unsigned long long a01 = 0, a23 = 0;
#pragma unroll
                for (int k0 = 0; k0 < 32; ++k0) {
                    ulonglong2 w = W4[(size_t)k0 * (GF_ / 4)];
                    unsigned long long hh = packf2(s.ht[kh * 32 + k0]);
                    ffma2(a01, w.x, hh);
                    ffma2(a23, w.y, hh);
                }
                float x0, x1, x2, x3;
                unpackf2(a01, x0, x1);
                unpackf2(a23, x2, x3);
                reinterpret_cast<float4*>(s.part)[kh * (GF_ / 4) + qg4] =
                    make_float4(x0, x1, x2, x3);
            }
            __syncthreads();
            {
                const float tbt_v = g_TBt[((size_t)b * NB_ + cb) * GF_ + t];
                const float tmt_v = g_TMt[((size_t)b * NM_ + cm) * GF_ + t];
                float acc = s.part[t] + s.part[GF_ + t] + s.part[2 * GF_ + t] + s.part[3 * GF_ + t]
                          + tbt_v + tmt_v;
                const float* wr = &s.Wtt[t * 11];
                acc += s.prev[0] * wr[0];
#pragma unroll
                for (int j = 0; j < D_; j++) acc += s.beat_res[j] * wr[1 + j];
                s.g[t] = acc;
            }
            __syncthreads();
            if (t < BH_) {
                float c2 = sigmoidf_(s.g[BH_ + t]) * s.ct[t]
                         + sigmoidf_(s.g[t]) * tanhf(s.g[2 * BH_ + t]);
                float h2 = sigmoidf_(s.g[3 * BH_ + t]) * tanhf(c2);
                s.ct[t] = c2;
                s.ht[t] = h2;
            }
            __syncthreads();
            if (wid == 0) {
                float p = s.ht[lane]      * s.Wtfc[lane]
                        + s.ht[lane + 32] * s.Wtfc[lane + 32]
                        + s.ht[lane + 64] * s.Wtfc[lane + 64]
                        + s.ht[lane + 96] * s.Wtfc[lane + 96];
                p = warp_sum_f(p);
                if (lane == 0) s.prev[0] = p + s.btfc;
            }
            __syncthreads();
            rs = i;  // new run starts here
        }

        // ---- final LSTM gates: hybrid k-split ----
        // kh 0,1 read Whh_f^T rows [0,64) from SMEM; kh 2,3 read rows [64,128) from global.
        {
            unsigned long long a01 = 0, a23 = 0;
            if (kh < 2) {
                const ulonglong2* W4 = reinterpret_cast<const ulonglong2*>(s.wsm)
                                     + (size_t)kh * 32 * (GF_ / 4) + qg4;
#pragma unroll
                for (int k0 = 0; k0 < 32; ++k0) {
                    ulonglong2 w = W4[(size_t)k0 * (GF_ / 4)];
                    unsigned long long hh = packf2(s.hf[kh * 32 + k0]);
                    ffma2(a01, w.x, hh);
                    ffma2(a23, w.y, hh);
                }
            } else {
                const ulonglong2* W4 = reinterpret_cast<const ulonglong2*>(g_WfT)
                                     + (size_t)kh * 32 * (GF_ / 4) + qg4;
#pragma unroll
                for (int k0 = 0; k0 < 32; ++k0) {
                    ulonglong2 w = W4[(size_t)k0 * (GF_ / 4)];
                    unsigned long long hh = packf2(s.hf[kh * 32 + k0]);
                    ffma2(a01, w.x, hh);
                    ffma2(a23, w.y, hh);
                }
            }
            float x0, x1, x2, x3;
            unpackf2(a01, x0, x1);
            unpackf2(a23, x2, x3);
            reinterpret_cast<float4*>(s.part)[kh * (GF_ / 4) + qg4] =
                make_float4(x0, x1, x2, x3);
        }
        __syncthreads();
        {
            float acc = s.part[t] + s.part[GF_ + t] + s.part[2 * GF_ + t] + s.part[3 * GF_ + t]
                      + gn_v + tbf_v + tmf_v;
            const float* wr = &s.Wtf[t * 11];
#pragma unroll
            for (int j = 0; j < OUT_; j++) acc += s.prev[j] * wr[j];
            s.g[t] = acc;
        }
        __syncthreads();
        if (t < FH_) {
            float c2 = sigmoidf_(s.g[FH_ + t]) * s.cf[t]
                     + sigmoidf_(s.g[t]) * tanhf(s.g[2 * FH_ + t]);
            float h2 = sigmoidf_(s.g[3 * FH_ + t]) * tanhf(c2);
            s.cf[t] = c2;
            s.hf[t] = h2;
        }
        __syncthreads();

        // ---- output fc + history + global write ----
        float* orow = out + ((size_t)b * N_ + i) * OUT_;
        if (wid < D_) {
            float p = s.hf[lane]      * s.Wfc[wid * FH_ + lane]
                    + s.hf[lane + 32] * s.Wfc[wid * FH_ + lane + 32]
                    + s.hf[lane + 64] * s.Wfc[wid * FH_ + lane + 64]
                    + s.hf[lane + 96] * s.Wfc[wid * FH_ + lane + 96];
            p = warp_sum_f(p);
            if (lane == 0) {
                float o = p + s.bfc[wid];
                s.prev[1 + wid] = o;
                s.hist[(i & (HR_ - 1)) * D_ + wid] = o;   // unmasked history
                orow[1 + wid] = pd ? 0.f : o;
            }
        } else if (t == 320) {
            orow[0] = pd ? 0.f : s.prev[0];
        }
        __syncthreads();
    }
}

// ---------------------------------------------------------------------------
// Launch
// ---------------------------------------------------------------------------
extern "C" void kernel_launch(void* const* d_in, const int* in_sizes, int n_in,
                              void* d_out, int out_size) {
    const float* note_emb        = (const float*)d_in[0];
    const float* beat_emb        = (const float*)d_in[1];
    const float* measure_emb     = (const float*)d_in[2];
    const int*   beat_numbers    = (const int*)d_in[3];
    const int*   measure_numbers = (const int*)d_in[4];
    const float* Wa    = (const float*)d_in[5];
    const float* ba    = (const float*)d_in[6];
    const float* ctx   = (const float*)d_in[7];
    const float* Wih_t = (const float*)d_in[8];
    const float* Whh_t = (const float*)d_in[9];
    const float* bih_t = (const float*)d_in[10];
    const float* bhh_t = (const float*)d_in[11];
    const float* Wih_f = (const float*)d_in[12];
    const float* Whh_f = (const float*)d_in[13];
    const float* bih_f = (const float*)d_in[14];
    const float* bhh_f = (const float*)d_in[15];
    const float* W_fc  = (const float*)d_in[16];
    const float* b_fc  = (const float*)d_in[17];
    const float* W_tfc = (const float*)d_in[18];
    const float* b_tfc = (const float*)d_in[19];
    float* out = (float*)d_out;

    float *pG, *pTBf, *pTMf, *pTBt, *pTMt, *pWfT, *pWtT;
    unsigned char* pPad;
    cudaGetSymbolAddress((void**)&pG,   g_Gnote);
    cudaGetSymbolAddress((void**)&pTBf, g_TBf);
    cudaGetSymbolAddress((void**)&pTMf, g_TMf);
    cudaGetSymbolAddress((void**)&pTBt, g_TBt);
    cudaGetSymbolAddress((void**)&pTMt, g_TMt);
    cudaGetSymbolAddress((void**)&pWfT, g_WfT);
    cudaGetSymbolAddress((void**)&pWtT, g_WtT);
    cudaGetSymbolAddress((void**)&pPad, g_pad);

    cudaFuncSetAttribute(scan_kernel, cudaFuncAttributeMaxDynamicSharedMemorySize,
                         (int)sizeof(ScanSmem));

    transpose_whh_kernel<<<256, 256>>>(Whh_f, pWfT);
    transpose_whh_kernel<<<256, 256>>>(Whh_t, pWtT);
    pad_kernel<<<B_ * N_, 128>>>(note_emb, pPad);

    // G_note = note_emb @ Wih_f[:, 0:512]^T          (32768 x 512 x 512)
    gemm_nt_kernel<<<dim3((B_ * N_) / GBM, GF_ / GBN), 256>>>(
        note_emb, NOTE_, NOTE_, Wih_f, LDF_, 0, pG, nullptr, nullptr);
    // TBf = beat_emb @ Wih_f[:, 512:640]^T
    gemm_nt_kernel<<<dim3((B_ * NB_) / GBM, GF_ / GBN), 256>>>(
        beat_emb, BH_, BH_, Wih_f, LDF_, NOTE_, pTBf, nullptr, nullptr);
    // TMf = measure_emb @ Wih_f[:, 640:704]^T + bih_f + bhh_f
    gemm_nt_kernel<<<dim3((B_ * NM_) / GBM, GF_ / GBN), 256>>>(
        measure_emb, MH_, MH_, Wih_f, LDF_, NOTE_ + BH_, pTMf, bih_f, bhh_f);
    // TBt = beat_emb @ Wih_t[:, 0:128]^T
    gemm_nt_kernel<<<dim3((B_ * NB_) / GBM, GF_ / GBN), 256>>>(
        beat_emb, BH_, BH_, Wih_t, LDT_, 0, pTBt, nullptr, nullptr);
    // TMt = measure_emb @ Wih_t[:, 128:192]^T + bih_t + bhh_t
    gemm_nt_kernel<<<dim3((B_ * NM_) / GBM, GF_ / GBN), 256>>>(
        measure_emb, MH_, MH_, Wih_t, LDT_, BH_, pTMt, bih_t, bhh_t);

    scan_kernel<<<B_, 512, sizeof(ScanSmem)>>>(
        beat_numbers, measure_numbers, Wa, ba, ctx,
        Wih_t, Wih_f, W_fc, b_fc, W_tfc, b_tfc, out);

    (void)in_sizes; (void)n_in; (void)out_size;
}

// round 7
// speedup vs baseline: 1.7377x; 1.0515x over previous
#include <cuda_runtime.h>
#include <cuda_bf16.h>
#include <math.h>
#include <stdint.h>

// ---------------------------------------------------------------------------
// Problem constants
// ---------------------------------------------------------------------------
#define B_    16
#define N_    2048
#define NOTE_ 512
#define BH_   128     // BEAT_H
#define MH_   64      // MEAS_H
#define FH_   128     // FINAL_H
#define NB_   256     // NUM_BEATS
#define NM_   64      // NUM_MEAS
#define OUT_  11
#define D_    10      // OUT-1
#define GF_   512     // 4*FH == 4*BH
#define LDF_  715     // fin input width  (512+128+64+11)
#define LDT_  203     // tempo input width (128+64+1+10)
#define HR_   256     // history ring size (max beat-run << 256)

// ---------------------------------------------------------------------------
// Device scratch (static globals: allocation-free)
// ---------------------------------------------------------------------------
__device__ float g_Gnote[(size_t)B_ * N_ * GF_]; // note_emb @ Wih_f[:, :512]^T
__device__ float g_TBf[B_ * NB_ * GF_];          // beat_emb @ Wih_f[:, 512:640]^T
__device__ float g_TMf[B_ * NM_ * GF_];          // meas_emb @ Wih_f[:, 640:704]^T + biases
__device__ float g_TBt[B_ * NB_ * GF_];          // beat_emb @ Wih_t[:, :128]^T
__device__ float g_TMt[B_ * NM_ * GF_];          // meas_emb @ Wih_t[:, 128:192]^T + biases
__device__ float g_WfT[FH_ * GF_];               // Whh_f transposed: WT[k][gate]
__device__ float g_WtT[BH_ * GF_];               // Whh_t transposed: WT[k][gate]
__device__ unsigned char g_pad[B_ * N_];

// ---------------------------------------------------------------------------
// Helpers
// ---------------------------------------------------------------------------
__device__ __forceinline__ float warp_sum_f(float v) {
#pragma unroll
    for (int o = 16; o; o >>= 1) v += __shfl_xor_sync(0xffffffffu, v, o);
    return v;
}
__device__ __forceinline__ float warp_max_f(float v) {
#pragma unroll
    for (int o = 16; o; o >>= 1) v = fmaxf(v, __shfl_xor_sync(0xffffffffu, v, o));
    return v;
}
__device__ __forceinline__ float sigmoidf_(float x) {
    return 1.0f / (1.0f + expf(-x));
}
// packed fp32x2 FMA (sm_100+): d = a*b + d on two lanes at once
__device__ __forceinline__ void ffma2(unsigned long long& d, unsigned long long a,
                                      unsigned long long b) {
    asm("fma.rn.f32x2 %0, %1, %2, %0;" : "+l"(d) : "l"(a), "l"(b));
}
__device__ __forceinline__ unsigned long long packf2(float h) {
    unsigned long long r;
    unsigned int u = __float_as_uint(h);
    asm("mov.b64 %0, {%1, %1};" : "=l"(r) : "r"(u));
    return r;
}
__device__ __forceinline__ void unpackf2(unsigned long long v, float& lo, float& hi) {
    asm("mov.b64 {%0, %1}, %2;" : "=f"(lo), "=f"(hi) : "l"(v));
}
__device__ __forceinline__ uint32_t smem_u32(const void* p) {
    uint32_t a;
    asm("{ .reg .u64 t; cvta.to.shared.u64 t, %1; cvt.u32.u64 %0, t; }"
        : "=r"(a) : "l"(p));
    return a;
}
__device__ __forceinline__ uint32_t mapa_peer(uint32_t addr, uint32_t peer) {
    uint32_t r;
    asm("mapa.shared::cluster.u32 %0, %1, %2;" : "=r"(r) : "r"(addr), "r"(peer));
    return r;
}
__device__ __forceinline__ void st_cluster_f32(uint32_t addr, float v) {
    asm volatile("st.shared::cluster.f32 [%0], %1;" :: "r"(addr), "f"(v) : "memory");
}
__device__ __forceinline__ void fence_cluster() {
    asm volatile("fence.acq_rel.cluster;" ::: "memory");
}
__device__ __forceinline__ void mbar_init(uint32_t addr, uint32_t count) {
    asm volatile("mbarrier.init.shared.b64 [%0], %1;" :: "r"(addr), "r"(count) : "memory");
}
__device__ __forceinline__ void mbar_arrive_cluster(uint32_t cluster_addr) {
    asm volatile("mbarrier.arrive.shared::cluster.b64 _, [%0];"
                 :: "r"(cluster_addr) : "memory");
}
__device__ __forceinline__ void mbar_wait_parity(uint32_t addr, uint32_t parity) {
    uint32_t done;
    asm volatile(
        "{ .reg .pred p;\n\t"
        "mbarrier.try_wait.parity.acquire.cta.shared::cta.b64 p, [%1], %2, 0x989680;\n\t"
        "selp.b32 %0, 1, 0, p; }"
        : "=r"(done) : "r"(addr), "r"(parity) : "memory");
    while (!done) {
        asm volatile(
            "{ .reg .pred p;\n\t"
            "mbarrier.try_wait.parity.acquire.cta.shared::cta.b64 p, [%1], %2, 0x989680;\n\t"
            "selp.b32 %0, 1, 0, p; }"
            : "=r"(done) : "r"(addr), "r"(parity) : "memory");
    }
}
#define CLUSTER_SYNC_() do { \
    asm volatile("barrier.cluster.arrive.aligned;" ::: "memory"); \
    asm volatile("barrier.cluster.wait.aligned;" ::: "memory"); \
} while (0)

// ---------------------------------------------------------------------------
// Transpose Whh (512 x 128) -> WT (128 x 512)
// ---------------------------------------------------------------------------
__global__ void transpose_whh_kernel(const float* __restrict__ W, float* __restrict__ WT) {
    int idx = blockIdx.x * 256 + threadIdx.x;   // 65536 elements
    int g = idx >> 7;
    int k = idx & 127;
    WT[k * GF_ + g] = W[idx];
}

// ---------------------------------------------------------------------------
// pad[row] = (sum(note_emb[row, :]) == 0)
// ---------------------------------------------------------------------------
__global__ void pad_kernel(const float* __restrict__ note, unsigned char* __restrict__ pad) {
    int row = blockIdx.x;
    float s = 0.f;
    for (int k = threadIdx.x; k < NOTE_; k += 128) s += note[(size_t)row * NOTE_ + k];
    s = warp_sum_f(s);
    __shared__ float red[4];
    if ((threadIdx.x & 31) == 0) red[threadIdx.x >> 5] = s;
    __syncthreads();
    if (threadIdx.x == 0)
        pad[row] = ((red[0] + red[1] + red[2] + red[3]) == 0.0f) ? 1 : 0;
}

// ---------------------------------------------------------------------------
// GEMM: C[M x 512] = A[M x K] @ W(rows of length ldw, cols [cofs, cofs+K))^T
// BM=128, BN=64, BK=16, 256 threads, 8x4 microtile, double-buffered smem.
// ---------------------------------------------------------------------------
#define GBM 128
#define GBN 64
#define GBK 16

__global__ void __launch_bounds__(256) gemm_nt_kernel(
    const float* __restrict__ A, int lda, int K,
    const float* __restrict__ W, int ldw, int cofs,
    float* __restrict__ C,
    const float* __restrict__ bias0, const float* __restrict__ bias1)
{
    __shared__ __align__(16) float As[2][GBK][GBM + 4];
    __shared__ __align__(16) float Bs[2][GBK][GBN];

    const int m0 = blockIdx.x * GBM;
    const int n0 = blockIdx.y * GBN;
    const int t  = threadIdx.x;
    const int tx = t & 15;
    const int ty = t >> 4;

    const int a_row = t >> 2;
    const int a_c4  = t & 3;
    float acc[8][4];
#pragma unroll
    for (int r = 0; r < 8; r++)
#pragma unroll
        for (int c = 0; c < 4; c++) acc[r][c] = 0.f;

    const int nk = K / GBK;

    {
#pragma unroll
        for (int rr = 0; rr < 2; rr++) {
            int row = a_row + rr * 64;
            float4 av = *(const float4*)(A + (size_t)(m0 + row) * lda + a_c4 * 4);
            As[0][a_c4 * 4 + 0][row] = av.x;
            As[0][a_c4 * 4 + 1][row] = av.y;
            As[0][a_c4 * 4 + 2][row] = av.z;
            As[0][a_c4 * 4 + 3][row] = av.w;
        }
#pragma unroll
        for (int rr = 0; rr < 4; rr++) {
            int f = t + rr * 256;
            int kk = f & 15;
            int n = f >> 4;
            Bs[0][kk][n] = W[(size_t)(n0 + n) * ldw + cofs + kk];
        }
    }
    __syncthreads();

    for (int kt = 0; kt < nk; ++kt) {
        const int cur = kt & 1;
        const int nxt = cur ^ 1;
        if (kt + 1 < nk) {
            const int k0 = (kt + 1) * GBK;
#pragma unroll
            for (int rr = 0; rr < 2; rr++) {
                int row = a_row + rr * 64;
                float4 av = *(const float4*)(A + (size_t)(m0 + row) * lda + k0 + a_c4 * 4);
                As[nxt][a_c4 * 4 + 0][row] = av.x;
                As[nxt][a_c4 * 4 + 1][row] = av.y;
                As[nxt][a_c4 * 4 + 2][row] = av.z;
                As[nxt][a_c4 * 4 + 3][row] = av.w;
            }
#pragma unroll
            for (int rr = 0; rr < 4; rr++) {
                int f = t + rr * 256;
                int kk = f & 15;
                int n = f >> 4;
                Bs[nxt][kk][n] = W[(size_t)(n0 + n) * ldw + cofs + k0 + kk];
            }
        }
#pragma unroll
        for (int kk = 0; kk < GBK; kk++) {
            float4 a0 = *(const float4*)&As[cur][kk][ty * 8];
            float4 a1 = *(const float4*)&As[cur][kk][ty * 8 + 4];
            float4 bv = *(const float4*)&Bs[cur][kk][tx * 4];
            float av[8] = {a0.x, a0.y, a0.z, a0.w, a1.x, a1.y, a1.z, a1.w};
            float bb[4] = {bv.x, bv.y, bv.z, bv.w};
#pragma unroll
            for (int r = 0; r < 8; r++)
#pragma unroll
                for (int c = 0; c < 4; c++) acc[r][c] += av[r] * bb[c];
        }
        __syncthreads();
    }

    const int gbase = n0 + tx * 4;
#pragma unroll
    for (int r = 0; r < 8; r++) {
        int m = m0 + ty * 8 + r;
        float4 v = make_float4(acc[r][0], acc[r][1], acc[r][2], acc[r][3]);
        if (bias0) {
            v.x += bias0[gbase + 0] + bias1[gbase + 0];
            v.y += bias0[gbase + 1] + bias1[gbase + 1];
            v.z += bias0[gbase + 2] + bias1[gbase + 2];
            v.w += bias0[gbase + 3] + bias1[gbase + 3];
        }
        *(float4*)&C[(size_t)m * GF_ + gbase] = v;
    }
}

// ---------------------------------------------------------------------------
// Persistent scan kernel: 2-CTA cluster per batch. Each CTA owns 64 hf units
// (256 gates); its half of Whh_f^T lives ENTIRELY in SMEM. h halves exchanged
// per step via DSMEM + mbarrier. Tempo LSTM / attention / fc replicated.
// ---------------------------------------------------------------------------
struct __align__(16) ScanSmem {
    float wsm[128 * 256];     // local half of Whh_f^T: wsm[k][g4*64+u]  (128 KB)
    float part[2048];         // partials (final: [8][256], tempo: [4][512])
    float Wtf[GF_ * 11];      // Wih_f[:, 704:715] (global-gate indexed)
    float Wtt[GF_ * 11];      // Wih_t[:, 192:203]
    float Wfc[D_ * FH_];      // W_fc
    float g[GF_];             // tempo gate preactivations
    float Wtfc[BH_];          // W_tfc
    float hfbuf[2][FH_];      // ping-pong full hf (own half local, peer via DSMEM)
    float cfloc[64];          // local cf half
    float ht[BH_], ct[BH_];   // replicated tempo state
    float hist[HR_ * D_];     // replicated output history ring
    float prev[16];           // prev_out (11 used)
    float beat_res[16];
    float va[16];
    float bfc[16];
    float c0;
    float btfc;
    unsigned long long mbar;  // exchange barrier (64 arrivals from peer)
    unsigned char cbA[N_];
    unsigned char cmA[N_];
    unsigned char chA[N_];
};

__global__ void __launch_bounds__(512, 1) __cluster_dims__(2, 1, 1) scan_kernel(
    const int* __restrict__ beat_numbers, const int* __restrict__ measure_numbers,
    const float* __restrict__ Wa, const float* __restrict__ ba, const float* __restrict__ ctx,
    const float* __restrict__ Wih_t, const float* __restrict__ Wih_f,
    const float* __restrict__ W_fc, const float* __restrict__ b_fc,
    const float* __restrict__ W_tfc, const float* __restrict__ b_tfc,
    float* __restrict__ out)
{
    extern __shared__ char smem_raw[];
    ScanSmem& s = *reinterpret_cast<ScanSmem*>(smem_raw);

    const int t    = threadIdx.x;
    const int lane = t & 31;
    const int wid  = t >> 5;
    uint32_t rank;
    asm("mov.u32 %0, %%cluster_ctarank;" : "=r"(rank));
    const int b = blockIdx.x >> 1;
    const uint32_t peer = rank ^ 1u;

    // ---- init shared state ----
    for (int idx = t; idx < 128 * 256; idx += 512) {
        int k = idx >> 8, l = idx & 255;
        int g4 = l >> 6, u = l & 63;
        s.wsm[idx] = g_WfT[k * GF_ + g4 * 128 + (int)rank * 64 + u];
    }
    for (int idx = t; idx < GF_ * 11; idx += 512) {
        int gg = idx / 11, j = idx - gg * 11;
        s.Wtf[idx] = Wih_f[(size_t)gg * LDF_ + 704 + j];
        s.Wtt[idx] = Wih_t[(size_t)gg * LDT_ + 192 + j];
    }
    for (int idx = t; idx < D_ * FH_; idx += 512) s.Wfc[idx] = W_fc[idx];
    if (t < BH_) { s.Wtfc[t] = W_tfc[t]; s.ht[t] = 0.f; s.ct[t] = 0.f; }
    if (t < FH_) { s.hfbuf[0][t] = 0.f; s.hfbuf[1][t] = 0.f; }
    if (t < 64)  s.cfloc[t] = 0.f;
    if (t < D_)  s.bfc[t] = b_fc[t];
    if (t < 16)  { s.prev[t] = 0.f; s.beat_res[t] = 0.f; }
    if (t < D_) {
        float v = 0.f;
#pragma unroll
        for (int k = 0; k < D_; k++) v += ctx[k] * Wa[k * D_ + t];
        s.va[t] = v;
    }
    if (t == 0) {
        float v = 0.f;
#pragma unroll
        for (int k = 0; k < D_; k++) v += ba[k] * ctx[k];
        s.c0 = v;
        s.btfc = b_tfc[0];
        mbar_init(smem_u32(&s.mbar), 64);
    }
    {
        const int beat0 = beat_numbers[b * N_];
        const int meas0 = measure_numbers[b * N_];
        for (int i = t; i < N_; i += 512) {
            int bi = beat_numbers[b * N_ + i];
            int mi = measure_numbers[b * N_ + i];
            s.cbA[i] = (unsigned char)(bi - beat0);
            s.cmA[i] = (unsigned char)(mi - meas0);
            s.chA[i] = (i == 0) ? 1 : ((bi != beat_numbers[b * N_ + i - 1]) ? 1 : 0);
        }
    }
    __syncthreads();
    CLUSTER_SYNC_();   // mbarriers + SMEM ready before any remote traffic

    const uint32_t mbar_local = smem_u32(&s.mbar);
    const uint32_t mbar_peer  = mapa_peer(mbar_local, peer);

    int rs = 0;        // start of current beat run (uniform)
    uint32_t ph = 0;   // mbarrier phase parity

    for (int i = 0; i < N_; ++i) {
        const int rd = (i + 1) & 1;   // holds h(i-1)
        const int wr = i & 1;         // will hold h(i)
        const int cb = s.cbA[i];
        const int cm = s.cmA[i];
        const bool changed = (s.chA[i] != 0);

        // -- prefetch input-sum for this CTA's 4 gates per unit (threads t<64) --
        float in_g[4];
        if (t < 64) {
#pragma unroll
            for (int g4 = 0; g4 < 4; g4++) {
                int Gg = g4 * 128 + (int)rank * 64 + t;
                in_g[g4] = g_Gnote[((size_t)b * N_ + i) * GF_ + Gg]
                         + g_TBf[((size_t)b * NB_ + cb) * GF_ + Gg]
                         + g_TMf[((size_t)b * NM_ + cm) * GF_ + Gg];
            }
        }

        // -- fc of step i-1 (reads hfbuf[rd]) --
        if (i > 0) {
            const int j = i - 1;
            if (wid < D_) {
                const float* hfb = s.hfbuf[rd];
                float p = hfb[lane]      * s.Wfc[wid * FH_ + lane]
                        + hfb[lane + 32] * s.Wfc[wid * FH_ + lane + 32]
                        + hfb[lane + 64] * s.Wfc[wid * FH_ + lane + 64]
                        + hfb[lane + 96] * s.Wfc[wid * FH_ + lane + 96];
                p = warp_sum_f(p);
                if (lane == 0) {
                    float o = p + s.bfc[wid];
                    s.prev[1 + wid] = o;
                    s.hist[(j & (HR_ - 1)) * D_ + wid] = o;
                    if (rank == 0) {
                        bool pd = (g_pad[b * N_ + j] != 0);
                        out[((size_t)b * N_ + j) * OUT_ + 1 + wid] = pd ? 0.f : o;
                    }
                }
            } else if (t == 320 && rank == 0) {
                bool pd = (g_pad[b * N_ + j] != 0);
                out[((size_t)b * N_ + j) * OUT_] = pd ? 0.f : s.prev[0];
            }
        }

        if (changed) {
            __syncthreads();   // hist/prev from fc visible
            // ---- attention over previous beat run [rs, i) (warp 0) ----
            if (i > 0 && wid == 0) {
                float mx = -1e30f;
                for (int n = rs + lane; n < i; n += 32) {
                    const float* hrow = &s.hist[(n & (HR_ - 1)) * D_];
                    float sim = s.c0;
#pragma unroll
                    for (int j = 0; j < D_; j++) sim += hrow[j] * s.va[j];
                    mx = fmaxf(mx, sim);
                }
                mx = warp_max_f(mx);
                float ssum = 0.f;
                float acc[D_];
#pragma unroll
                for (int j = 0; j < D_; j++) acc[j] = 0.f;
                for (int n = rs + lane; n < i; n += 32) {
                    const float* hrow = &s.hist[(n & (HR_ - 1)) * D_];
                    float sim = s.c0;
#pragma unroll
                    for (int j = 0; j < D_; j++) sim += hrow[j] * s.va[j];
                    float e = expf(sim - mx);
                    ssum += e;
#pragma unroll
                    for (int j = 0; j < D_; j++) acc[j] += e * hrow[j];
                }
                ssum = warp_sum_f(ssum);
#pragma unroll
                for (int j = 0; j < D_; j++) acc[j] = warp_sum_f(acc[j]);
                if (lane == 0) {
                    float inv = 1.0f / ssum;
#pragma unroll
                    for (int j = 0; j < D_; j++) s.beat_res[j] = acc[j] * inv;
                }
            }

            // ---- tempo LSTM gate partials (replicated; stream g_WtT global) ----
            {
                const int qg4 = t & 127;
                const int kh  = t >> 7;
                const ulonglong2* W4 = reinterpret_cast<const ulonglong2*>(g_WtT)
                                     + (size_t)kh * 32 * (GF_ / 4) + qg4;
                unsigned long long a01 = 0, a23 = 0;
#pragma unroll
                for (int k0 = 0; k0 < 32; ++k0) {
                    ulonglong2 w = W4[(size_t)k0 * (GF_ / 4)];
                    unsigned long long hh = packf2(s.ht[kh * 32 + k0]);
                    ffma2(a01, w.x, hh);
                    ffma2(a23, w.y, hh);
                }
                float x0, x1, x2, x3;
                unpackf2(a01, x0, x1);
                unpackf2(a23, x2, x3);
                *reinterpret_cast<float4*>(&s.part[kh * GF_ + 4 * qg4]) =
                    make_float4(x0, x1, x2, x3);
            }
            __syncthreads();
            // ---- assemble tempo gates ----
            {
                float acc = s.part[t] + s.part[GF_ + t]
                          + s.part[2 * GF_ + t] + s.part[3 * GF_ + t]
                          + g_TBt[((size_t)b * NB_ + cb) * GF_ + t]
                          + g_TMt[((size_t)b * NM_ + cm) * GF_ + t];
                const float* wr2 = &s.Wtt[t * 11];
                acc += s.prev[0] * wr2[0];
#pragma unroll
                for (int j = 0; j < D_; j++) acc += s.beat_res[j] * wr2[1 + j];
                s.g[t] = acc;
            }
            __syncthreads();
            if (t < BH_) {
                float c2 = sigmoidf_(s.g[BH_ + t]) * s.ct[t]
                         + sigmoidf_(s.g[t]) * tanhf(s.g[2 * BH_ + t]);
                float h2 = sigmoidf_(s.g[3 * BH_ + t]) * tanhf(c2);
                s.ct[t] = c2;
                s.ht[t] = h2;
            }
            __syncthreads();
            if (wid == 0) {
                float p = s.ht[lane]      * s.Wtfc[lane]
                        + s.ht[lane + 32] * s.Wtfc[lane + 32]
                        + s.ht[lane + 64] * s.Wtfc[lane + 64]
                        + s.ht[lane + 96] * s.Wtfc[lane + 96];
                p = warp_sum_f(p);
                if (lane == 0) s.prev[0] = p + s.btfc;
            }
            rs = i;
        }

        // ---- final LSTM gate partials: all-SMEM weight stream ----
        {
            const int q  = t & 63;    // gate-quad (local gates 4q..4q+3)
            const int ks = t >> 6;    // k slice [16ks, 16ks+16)
            const float* hfb = s.hfbuf[rd];
            float hreg[16];
            {
                const float4* h4 = reinterpret_cast<const float4*>(hfb + ks * 16);
#pragma unroll
                for (int m = 0; m < 4; m++) {
                    float4 hv = h4[m];
                    hreg[4 * m + 0] = hv.x; hreg[4 * m + 1] = hv.y;
                    hreg[4 * m + 2] = hv.z; hreg[4 * m + 3] = hv.w;
                }
            }
            const ulonglong2* W2 = reinterpret_cast<const ulonglong2*>(s.wsm);
            unsigned long long a01 = 0, a23 = 0;
#pragma unroll
            for (int k0 = 0; k0 < 16; ++k0) {
                ulonglong2 w = W2[(16 * ks + k0) * 64 + q];
                unsigned long long hh = packf2(hreg[k0]);
                ffma2(a01, w.x, hh);
                ffma2(a23, w.y, hh);
            }
            float x0, x1, x2, x3;
            unpackf2(a01, x0, x1);
            unpackf2(a23, x2, x3);
            *reinterpret_cast<float4*>(&s.part[ks * 256 + 4 * q]) =
                make_float4(x0, x1, x2, x3);
        }
        __syncthreads();   // sync1

        // ---- cell update for this CTA's 64 units + exchange ----
        if (t < 64) {
            float gg[4];
#pragma unroll
            for (int g4 = 0; g4 < 4; g4++) {
                int l = g4 * 64 + t;
                float acc = in_g[g4];
#pragma unroll
                for (int ks = 0; ks < 8; ks++) acc += s.part[ks * 256 + l];
                int Gg = g4 * 128 + (int)rank * 64 + t;
                const float* wr2 = &s.Wtf[Gg * 11];
#pragma unroll
                for (int j = 0; j < OUT_; j++) acc += s.prev[j] * wr2[j];
                gg[g4] = acc;
            }
            float c2 = sigmoidf_(gg[1]) * s.cfloc[t] + sigmoidf_(gg[0]) * tanhf(gg[2]);
            float h2 = sigmoidf_(gg[3]) * tanhf(c2);
            s.cfloc[t] = c2;
            int slot = (int)rank * 64 + t;
            s.hfbuf[wr][slot] = h2;
            uint32_t la = smem_u32(&s.hfbuf[wr][slot]);
            st_cluster_f32(mapa_peer(la, peer), h2);
            fence_cluster();                       // release my store
            mbar_arrive_cluster(mbar_peer);        // arrive on peer (count 64)
        }
        __syncthreads();   // sync2: local half + part consumption complete

        mbar_wait_parity(mbar_local, ph);          // peer half arrived
        fence_cluster();                           // acquire peer stores
        ph ^= 1;
    }

    // ---- epilogue: fc + write for step N-1 ----
    {
        const int j = N_ - 1;
        const int bidx = j & 1;
        if (wid < D_) {
            const float* hfb = s.hfbuf[bidx];
            float p = hfb[lane]      * s.Wfc[wid * FH_ + lane]
                    + hfb[lane + 32] * s.Wfc[wid * FH_ + lane + 32]
                    + hfb[lane + 64] * s.Wfc[wid * FH_ + lane + 64]
                    + hfb[lane + 96] * s.Wfc[wid * FH_ + lane + 96];
            p = warp_sum_f(p);
            if (lane == 0 && rank == 0) {
                float o = p + s.bfc[wid];
                bool pd = (g_pad[b * N_ + j] != 0);
                out[((size_t)b * N_ + j) * OUT_ + 1 + wid] = pd ? 0.f : o;
            }
        } else if (t == 320 && rank == 0) {
            bool pd = (g_pad[b * N_ + j] != 0);
            out[((size_t)b * N_ + j) * OUT_] = pd ? 0.f : s.prev[0];
        }
    }
    CLUSTER_SYNC_();   // no CTA exits while peer traffic may be in flight
}

// ---------------------------------------------------------------------------
// Launch
// ---------------------------------------------------------------------------
extern "C" void kernel_launch(void* const* d_in, const int* in_sizes, int n_in,
                              void* d_out, int out_size) {
    const float* note_emb        = (const float*)d_in[0];
    const float* beat_emb        = (const float*)d_in[1];
    const float* measure_emb     = (const float*)d_in[2];
    const int*   beat_numbers    = (const int*)d_in[3];
    const int*   measure_numbers = (const int*)d_in[4];
    const float* Wa    = (const float*)d_in[5];
    const float* ba    = (const float*)d_in[6];
    const float* ctx   = (const float*)d_in[7];
    const float* Wih_t = (const float*)d_in[8];
    const float* Whh_t = (const float*)d_in[9];
    const float* bih_t = (const float*)d_in[10];
    const float* bhh_t = (const float*)d_in[11];
    const float* Wih_f = (const float*)d_in[12];
    const float* Whh_f = (const float*)d_in[13];
    const float* bih_f = (const float*)d_in[14];
    const float* bhh_f = (const float*)d_in[15];
    const float* W_fc  = (const float*)d_in[16];
    const float* b_fc  = (const float*)d_in[17];
    const float* W_tfc = (const float*)d_in[18];
    const float* b_tfc = (const float*)d_in[19];
    float* out = (float*)d_out;

    float *pG, *pTBf, *pTMf, *pTBt, *pTMt, *pWfT, *pWtT;
    unsigned char* pPad;
    cudaGetSymbolAddress((void**)&pG,   g_Gnote);
    cudaGetSymbolAddress((void**)&pTBf, g_TBf);
    cudaGetSymbolAddress((void**)&pTMf, g_TMf);
    cudaGetSymbolAddress((void**)&pTBt, g_TBt);
    cudaGetSymbolAddress((void**)&pTMt, g_TMt);
    cudaGetSymbolAddress((void**)&pWfT, g_WfT);
    cudaGetSymbolAddress((void**)&pWtT, g_WtT);
    cudaGetSymbolAddress((void**)&pPad, g_pad);

    cudaFuncSetAttribute(scan_kernel, cudaFuncAttributeMaxDynamicSharedMemorySize,
                         (int)sizeof(ScanSmem));

    transpose_whh_kernel<<<256, 256>>>(Whh_f, pWfT);
    transpose_whh_kernel<<<256, 256>>>(Whh_t, pWtT);
    pad_kernel<<<B_ * N_, 128>>>(note_emb, pPad);

    gemm_nt_kernel<<<dim3((B_ * N_) / GBM, GF_ / GBN), 256>>>(
        note_emb, NOTE_, NOTE_, Wih_f, LDF_, 0, pG, nullptr, nullptr);
    gemm_nt_kernel<<<dim3((B_ * NB_) / GBM, GF_ / GBN), 256>>>(
        beat_emb, BH_, BH_, Wih_f, LDF_, NOTE_, pTBf, nullptr, nullptr);
    gemm_nt_kernel<<<dim3((B_ * NM_) / GBM, GF_ / GBN), 256>>>(
        measure_emb, MH_, MH_, Wih_f, LDF_, NOTE_ + BH_, pTMf, bih_f, bhh_f);
    gemm_nt_kernel<<<dim3((B_ * NB_) / GBM, GF_ / GBN), 256>>>(
        beat_emb, BH_, BH_, Wih_t, LDT_, 0, pTBt, nullptr, nullptr);
    gemm_nt_kernel<<<dim3((B_ * NM_) / GBM, GF_ / GBN), 256>>>(
        measure_emb, MH_, MH_, Wih_t, LDT_, BH_, pTMt, bih_t, bhh_t);

    scan_kernel<<<2 * B_, 512, sizeof(ScanSmem)>>>(
        beat_numbers, measure_numbers, Wa, ba, ctx,
        Wih_t, Wih_f, W_fc, b_fc, W_tfc, b_tfc, out);

    (void)in_sizes; (void)n_in; (void)out_size;
}

// round 10
// speedup vs baseline: 1.9524x; 1.1236x over previous
#include <cuda_runtime.h>
#include <cuda_bf16.h>
#include <math.h>
#include <stdint.h>

// ---------------------------------------------------------------------------
// Problem constants
// ---------------------------------------------------------------------------
#define B_    16
#define N_    2048
#define NOTE_ 512
#define BH_   128     // BEAT_H
#define MH_   64      // MEAS_H
#define FH_   128     // FINAL_H
#define NB_   256     // NUM_BEATS
#define NM_   64      // NUM_MEAS
#define OUT_  11
#define D_    10      // OUT-1
#define GF_   512     // 4*FH == 4*BH
#define LDF_  715     // fin input width  (512+128+64+11)
#define LDT_  203     // tempo input width (128+64+1+10)
#define HR_   256     // history ring size (max beat-run << 256)

// ---------------------------------------------------------------------------
// Device scratch (static globals: allocation-free)
// ---------------------------------------------------------------------------
__device__ float g_Gnote[(size_t)B_ * N_ * GF_]; // note_emb @ Wih_f[:, :512]^T
__device__ float g_TBf[B_ * NB_ * GF_];          // beat_emb @ Wih_f[:, 512:640]^T
__device__ float g_TMf[B_ * NM_ * GF_];          // meas_emb @ Wih_f[:, 640:704]^T + biases
__device__ float g_TBt[B_ * NB_ * GF_];          // beat_emb @ Wih_t[:, :128]^T
__device__ float g_TMt[B_ * NM_ * GF_];          // meas_emb @ Wih_t[:, 128:192]^T + biases
__device__ float g_WfT[FH_ * GF_];               // Whh_f transposed: WT[k][gate]
__device__ float g_WtT[BH_ * GF_];               // Whh_t transposed: WT[k][gate]
__device__ unsigned char g_pad[B_ * N_];

// ---------------------------------------------------------------------------
// Helpers
// ---------------------------------------------------------------------------
__device__ __forceinline__ float warp_sum_f(float v) {
#pragma unroll
    for (int o = 16; o; o >>= 1) v += __shfl_xor_sync(0xffffffffu, v, o);
    return v;
}
__device__ __forceinline__ float warp_max_f(float v) {
#pragma unroll
    for (int o = 16; o; o >>= 1) v = fmaxf(v, __shfl_xor_sync(0xffffffffu, v, o));
    return v;
}
// fast approx transcendentals (MUFU-based, ~2 ulp)
__device__ __forceinline__ float ex2f_(float x) {
    float r; asm("ex2.approx.f32 %0, %1;" : "=f"(r) : "f"(x)); return r;
}
__device__ __forceinline__ float rcpf_(float x) {
    float r; asm("rcp.approx.f32 %0, %1;" : "=f"(r) : "f"(x)); return r;
}
#define LOG2E_ 1.442695040888963f
__device__ __forceinline__ float sigmoidf_(float x) {
    return rcpf_(1.0f + ex2f_(-LOG2E_ * x));
}
__device__ __forceinline__ float tanhf_(float x) {
    float e = ex2f_(-2.0f * LOG2E_ * fabsf(x));   // in (0,1]
    float t = (1.0f - e) * rcpf_(1.0f + e);
    return copysignf(t, x);
}
__device__ __forceinline__ float expf_(float x) {   // x <= 0 here
    return ex2f_(LOG2E_ * x);
}
// packed fp32x2 FMA (sm_100+)
__device__ __forceinline__ void ffma2(unsigned long long& d, unsigned long long a,
                                      unsigned long long b) {
    asm("fma.rn.f32x2 %0, %1, %2, %0;" : "+l"(d) : "l"(a), "l"(b));
}
__device__ __forceinline__ unsigned long long packf2(float h) {
    unsigned long long r;
    unsigned int u = __float_as_uint(h);
    asm("mov.b64 %0, {%1, %1};" : "=l"(r) : "r"(u));
    return r;
}
__device__ __forceinline__ void unpackf2(unsigned long long v, float& lo, float& hi) {
    asm("mov.b64 {%0, %1}, %2;" : "=f"(lo), "=f"(hi) : "l"(v));
}
__device__ __forceinline__ uint32_t smem_u32(const void* p) {
    uint32_t a;
    asm("{ .reg .u64 t; cvta.to.shared.u64 t, %1; cvt.u32.u64 %0, t; }"
        : "=r"(a) : "l"(p));
    return a;
}
__device__ __forceinline__ uint32_t mapa_peer(uint32_t addr, uint32_t peer) {
    uint32_t r;
    asm("mapa.shared::cluster.u32 %0, %1, %2;" : "=r"(r) : "r"(addr), "r"(peer));
    return r;
}
__device__ __forceinline__ void st_cluster_f32(uint32_t addr, float v) {
    asm volatile("st.shared::cluster.f32 [%0], %1;" :: "r"(addr), "f"(v) : "memory");
}
__device__ __forceinline__ void mbar_init(uint32_t addr, uint32_t count) {
    asm volatile("mbarrier.init.shared.b64 [%0], %1;" :: "r"(addr), "r"(count) : "memory");
}
// release-arrive on peer mbar: orders prior st.shared::cluster (NO standalone fence
// => no CCTL.IVALL L1 flush)
__device__ __forceinline__ void mbar_arrive_release_cluster(uint32_t cluster_addr) {
    asm volatile("mbarrier.arrive.release.cluster.shared::cluster.b64 _, [%0];"
                 :: "r"(cluster_addr) : "memory");
}
__device__ __forceinline__ void mbar_wait_parity_acq_cluster(uint32_t addr, uint32_t parity) {
    uint32_t done;
    asm volatile(
        "{ .reg .pred p;\n\t"
        "mbarrier.try_wait.parity.acquire.cluster.shared::cta.b64 p, [%1], %2, 0x989680;\n\t"
        "selp.b32 %0, 1, 0, p; }"
        : "=r"(done) : "r"(addr), "r"(parity) : "memory");
    while (!done) {
        asm volatile(
            "{ .reg .pred p;\n\t"
            "mbarrier.try_wait.parity.acquire.cluster.shared::cta.b64 p, [%1], %2, 0x989680;\n\t"
            "selp.b32 %0, 1, 0, p; }"
            : "=r"(done) : "r"(addr), "r"(parity) : "memory");
    }
}
#define CLUSTER_SYNC_() do { \
    asm volatile("barrier.cluster.arrive.aligned;" ::: "memory"); \
    asm volatile("barrier.cluster.wait.aligned;" ::: "memory"); \
} while (0)

// ---------------------------------------------------------------------------
// Prep: both Whh transposes in one launch (blocks 0..255 -> Wf, 256..511 -> Wt)
// ---------------------------------------------------------------------------
__global__ void prep_kernel(const float* __restrict__ Wf, float* __restrict__ WfT,
                            const float* __restrict__ Wt, float* __restrict__ WtT) {
    int bb = blockIdx.x;
    const float* W = (bb < 256) ? Wf : Wt;
    float* WT = (bb < 256) ? WfT : WtT;
    int idx = (bb & 255) * 256 + threadIdx.x;   // 65536 elements
    int g = idx >> 7;
    int k = idx & 127;
    WT[k * GF_ + g] = W[idx];
}

// ---------------------------------------------------------------------------
// pad[row] = (sum(note_emb[row, :]) == 0)
// ---------------------------------------------------------------------------
__global__ void pad_kernel(const float* __restrict__ note, unsigned char* __restrict__ pad) {
    int row = blockIdx.x;
    float s = 0.f;
    for (int k = threadIdx.x; k < NOTE_; k += 128) s += note[(size_t)row * NOTE_ + k];
    s = warp_sum_f(s);
    __shared__ float red[4];
    if ((threadIdx.x & 31) == 0) red[threadIdx.x >> 5] = s;
    __syncthreads();
    if (threadIdx.x == 0)
        pad[row] = ((red[0] + red[1] + red[2] + red[3]) == 0.0f) ? 1 : 0;
}

// ---------------------------------------------------------------------------
// GEMM body: C[M x 512] = A[M x K] @ W(rows ldw, cols [cofs,cofs+K))^T
// BM=128, BN=64, BK=16, 256 threads, 8x4 microtile, double-buffered.
// ---------------------------------------------------------------------------
#define GBM 128
#define GBN 64
#define GBK 16

__device__ __forceinline__ void gemm_body(
    const float* __restrict__ A, int lda, int K,
    const float* __restrict__ W, int ldw, int cofs,
    float* __restrict__ C,
    const float* __restrict__ bias0, const float* __restrict__ bias1,
    int m0, int n0)
{
    __shared__ __align__(16) float As[2][GBK][GBM + 4];
    __shared__ __align__(16) float Bs[2][GBK][GBN];

    const int t  = threadIdx.x;
    const int tx = t & 15;
    const int ty = t >> 4;
    const int a_row = t >> 2;
    const int a_c4  = t & 3;
    float acc[8][4];
#pragma unroll
    for (int r = 0; r < 8; r++)
#pragma unroll
        for (int c = 0; c < 4; c++) acc[r][c] = 0.f;

    const int nk = K / GBK;
    {
#pragma unroll
        for (int rr = 0; rr < 2; rr++) {
            int row = a_row + rr * 64;
            float4 av = *(const float4*)(A + (size_t)(m0 + row) * lda + a_c4 * 4);
            As[0][a_c4 * 4 + 0][row] = av.x;
            As[0][a_c4 * 4 + 1][row] = av.y;
            As[0][a_c4 * 4 + 2][row] = av.z;
            As[0][a_c4 * 4 + 3][row] = av.w;
        }
#pragma unroll
        for (int rr = 0; rr < 4; rr++) {
            int f = t + rr * 256;
            int kk = f & 15;
            int n = f >> 4;
            Bs[0][kk][n] = W[(size_t)(n0 + n) * ldw + cofs + kk];
        }
    }
    __syncthreads();

    for (int kt = 0; kt < nk; ++kt) {
        const int cur = kt & 1;
        const int nxt = cur ^ 1;
        if (kt + 1 < nk) {
            const int k0 = (kt + 1) * GBK;
#pragma unroll
            for (int rr = 0; rr < 2; rr++) {
                int row = a_row + rr * 64;
                float4 av = *(const float4*)(A + (size_t)(m0 + row) * lda + k0 + a_c4 * 4);
                As[nxt][a_c4 * 4 + 0][row] = av.x;
                As[nxt][a_c4 * 4 + 1][row] = av.y;
                As[nxt][a_c4 * 4 + 2][row] = av.z;
                As[nxt][a_c4 * 4 + 3][row] = av.w;
            }
#pragma unroll
            for (int rr = 0; rr < 4; rr++) {
                int f = t + rr * 256;
                int kk = f & 15;
                int n = f >> 4;
                Bs[nxt][kk][n] = W[(size_t)(n0 + n) * ldw + cofs + k0 + kk];
            }
        }
#pragma unroll
        for (int kk = 0; kk < GBK; kk++) {
            float4 a0 = *(const float4*)&As[cur][kk][ty * 8];
            float4 a1 = *(const float4*)&As[cur][kk][ty * 8 + 4];
            float4 bv = *(const float4*)&Bs[cur][kk][tx * 4];
            float av[8] = {a0.x, a0.y, a0.z, a0.w, a1.x, a1.y, a1.z, a1.w};
            float bb[4] = {bv.x, bv.y, bv.z, bv.w};
#pragma unroll
            for (int r = 0; r < 8; r++)
#pragma unroll
                for (int c = 0; c < 4; c++) acc[r][c] += av[r] * bb[c];
        }
        __syncthreads();
    }

    const int gbase = n0 + tx * 4;
#pragma unroll
    for (int r = 0; r < 8; r++) {
        int m = m0 + ty * 8 + r;
        float4 v = make_float4(acc[r][0], acc[r][1], acc[r][2], acc[r][3]);
        if (bias0) {
            v.x += bias0[gbase + 0] + bias1[gbase + 0];
            v.y += bias0[gbase + 1] + bias1[gbase + 1];
            v.z += bias0[gbase + 2] + bias1[gbase + 2];
            v.w += bias0[gbase + 3] + bias1[gbase + 3];
        }
        *(float4*)&C[(size_t)m * GF_ + gbase] = v;
    }
}

__global__ void __launch_bounds__(256) gemm_nt_kernel(
    const float* __restrict__ A, int lda, int K,
    const float* __restrict__ W, int ldw, int cofs,
    float* __restrict__ C,
    const float* __restrict__ bias0, const float* __restrict__ bias1)
{
    gemm_body(A, lda, K, W, ldw, cofs, C, bias0, bias1,
              blockIdx.x * GBM, blockIdx.y * GBN);
}

// paired GEMM: z=0 -> (W0,cofs0,C0,b00,b01); z=1 -> (W1,cofs1,C1,b10,b11)
__global__ void __launch_bounds__(256) gemm_pair_kernel(
    const float* __restrict__ A, int lda, int K,
    const float* __restrict__ W0, int ldw0, int cofs0, float* __restrict__ C0,
    const float* __restrict__ b00, const float* __restrict__ b01,
    const float* __restrict__ W1, int ldw1, int cofs1, float* __restrict__ C1,
    const float* __restrict__ b10, const float* __restrict__ b11)
{
    if (blockIdx.z == 0)
        gemm_body(A, lda, K, W0, ldw0, cofs0, C0, b00, b01,
                  blockIdx.x * GBM, blockIdx.y * GBN);
    else
        gemm_body(A, lda, K, W1, ldw1, cofs1, C1, b10, b11,
                  blockIdx.x * GBM, blockIdx.y * GBN);
}

// ---------------------------------------------------------------------------
// Persistent scan kernel: 2-CTA cluster per batch. Each CTA owns 64 hf units
// (256 gates); its half of Whh_f^T lives ENTIRELY in SMEM. h halves exchanged
// per step via DSMEM + mbarrier (release-arrive / acquire-wait, no fences).
// ---------------------------------------------------------------------------
struct __align__(16) ScanSmem {
    float wsm[128 * 256];     // local half of Whh_f^T: wsm[k][g4*64+u]  (128 KB)
    float part[2048];         // partials (final: [8][256], tempo: [4][512])
    float Wtf[11 * GF_];      // Wih_f[:, 704:715] transposed: [j][gate]
    float Wtt[11 * GF_];      // Wih_t[:, 192:203] transposed: [j][gate]
    float Wfc[D_ * FH_];      // W_fc
    float g[GF_];             // tempo gate preactivations
    float Wtfc[BH_];          // W_tfc
    float hfbuf[2][FH_];      // ping-pong full hf (own half local, peer via DSMEM)
    float cfloc[64];          // local cf half
    float ht[BH_], ct[BH_];   // replicated tempo state
    float hist[HR_ * D_];     // replicated output history ring
    float prev[16];           // prev_out (11 used)
    float beat_res[16];
    float va[16];
    float bfc[16];
    float c0;
    float btfc;
    unsigned long long mbar;  // exchange barrier (64 arrivals from peer)
    unsigned char cbA[N_];
    unsigned char cmA[N_];
    unsigned char chA[N_];
};

__global__ void __launch_bounds__(512, 1) __cluster_dims__(2, 1, 1) scan_kernel(
    const int* __restrict__ beat_numbers, const int* __restrict__ measure_numbers,
    const float* __restrict__ Wa, const float* __restrict__ ba, const float* __restrict__ ctx,
    const float* __restrict__ Wih_t, const float* __restrict__ Wih_f,
    const float* __restrict__ W_fc, const float* __restrict__ b_fc,
    const float* __restrict__ W_tfc, const float* __restrict__ b_tfc,
    float* __restrict__ out)
{
    extern __shared__ char smem_raw[];
    ScanSmem& s = *reinterpret_cast<ScanSmem*>(smem_raw);

    const int t    = threadIdx.x;
    const int lane = t & 31;
    const int wid  = t >> 5;
    uint32_t rank;
    asm("mov.u32 %0, %%cluster_ctarank;" : "=r"(rank));
    const int b = blockIdx.x >> 1;
    const uint32_t peer = rank ^ 1u;

    // ---- init shared state ----
    for (int idx = t; idx < 128 * 256; idx += 512) {
        int k = idx >> 8, l = idx & 255;
        int g4 = l >> 6, u = l & 63;
        s.wsm[idx] = g_WfT[k * GF_ + g4 * 128 + (int)rank * 64 + u];
    }
    for (int idx = t; idx < 11 * GF_; idx += 512) {
        int j = idx >> 9, gg = idx & 511;
        s.Wtf[idx] = Wih_f[(size_t)gg * LDF_ + 704 + j];
        s.Wtt[idx] = Wih_t[(size_t)gg * LDT_ + 192 + j];
    }
    for (int idx = t; idx < D_ * FH_; idx += 512) s.Wfc[idx] = W_fc[idx];
    if (t < BH_) { s.Wtfc[t] = W_tfc[t]; s.ht[t] = 0.f; s.ct[t] = 0.f; }
    if (t < FH_) { s.hfbuf[0][t] = 0.f; s.hfbuf[1][t] = 0.f; }
    if (t < 64)  s.cfloc[t] = 0.f;
    if (t < D_)  s.bfc[t] = b_fc[t];
    if (t < 16)  { s.prev[t] = 0.f; s.beat_res[t] = 0.f; }
    if (t < D_) {
        float v = 0.f;
#pragma unroll
        for (int k = 0; k < D_; k++) v += ctx[k] * Wa[k * D_ + t];
        s.va[t] = v;
    }
    if (t == 0) {
        float v = 0.f;
#pragma unroll
        for (int k = 0; k < D_; k++) v += ba[k] * ctx[k];
        s.c0 = v;
        s.btfc = b_tfc[0];
        mbar_init(smem_u32(&s.mbar), 64);
    }
    {
        const int beat0 = beat_numbers[b * N_];
        const int meas0 = measure_numbers[b * N_];
        for (int i = t; i < N_; i += 512) {
            int bi = beat_numbers[b * N_ + i];
            int mi = measure_numbers[b * N_ + i];
            s.cbA[i] = (unsigned char)(bi - beat0);
            s.cmA[i] = (unsigned char)(mi - meas0);
            s.chA[i] = (i == 0) ? 1 : ((bi != beat_numbers[b * N_ + i - 1]) ? 1 : 0);
        }
    }
    __syncthreads();
    CLUSTER_SYNC_();   // mbarriers + SMEM ready before any remote traffic

    const uint32_t mbar_local = smem_u32(&s.mbar);
    const uint32_t mbar_peer  = mapa_peer(mbar_local, peer);

    int rs = 0;        // start of current beat run (uniform)
    uint32_t ph = 0;   // mbarrier phase parity

    for (int i = 0; i < N_; ++i) {
        const int rd = (i + 1) & 1;   // holds h(i-1)
        const int wr = i & 1;         // will hold h(i)
        const int cb = s.cbA[i];
        const int cm = s.cmA[i];
        const bool changed = (s.chA[i] != 0);

        // -- prefetch input-sum for this CTA's 4 gates per unit (threads t<64) --
        float in_g[4];
        if (t < 64) {
#pragma unroll
            for (int g4 = 0; g4 < 4; g4++) {
                int Gg = g4 * 128 + (int)rank * 64 + t;
                in_g[g4] = __ldg(&g_Gnote[((size_t)b * N_ + i) * GF_ + Gg])
                         + __ldg(&g_TBf[((size_t)b * NB_ + cb) * GF_ + Gg])
                         + __ldg(&g_TMf[((size_t)b * NM_ + cm) * GF_ + Gg]);
            }
        }

        // -- fc of step i-1 (reads hfbuf[rd]) --
        if (i > 0) {
            const int j = i - 1;
            if (wid < D_) {
                const float* hfb = s.hfbuf[rd];
                float p = hfb[lane]      * s.Wfc[wid * FH_ + lane]
                        + hfb[lane + 32] * s.Wfc[wid * FH_ + lane + 32]
                        + hfb[lane + 64] * s.Wfc[wid * FH_ + lane + 64]
                        + hfb[lane + 96] * s.Wfc[wid * FH_ + lane + 96];
                p = warp_sum_f(p);
                if (lane == 0) {
                    float o = p + s.bfc[wid];
                    s.prev[1 + wid] = o;
                    s.hist[(j & (HR_ - 1)) * D_ + wid] = o;
                    if (rank == 0) {
                        bool pd = (g_pad[b * N_ + j] != 0);
                        out[((size_t)b * N_ + j) * OUT_ + 1 + wid] = pd ? 0.f : o;
                    }
                }
            } else if (t == 320 && rank == 0) {
                bool pd = (g_pad[b * N_ + j] != 0);
                out[((size_t)b * N_ + j) * OUT_] = pd ? 0.f : s.prev[0];
            }
        }

        if (changed) {
            __syncthreads();   // hist/prev from fc visible
            // ---- attention over previous beat run [rs, i) (warp 0) ----
            if (i > 0 && wid == 0) {
                float mx = -1e30f;
                for (int n = rs + lane; n < i; n += 32) {
                    const float* hrow = &s.hist[(n & (HR_ - 1)) * D_];
                    float sim = s.c0;
#pragma unroll
                    for (int j = 0; j < D_; j++) sim += hrow[j] * s.va[j];
                    mx = fmaxf(mx, sim);
                }
                mx = warp_max_f(mx);
                float ssum = 0.f;
                float acc[D_];
#pragma unroll
                for (int j = 0; j < D_; j++) acc[j] = 0.f;
                for (int n = rs + lane; n < i; n += 32) {
                    const float* hrow = &s.hist[(n & (HR_ - 1)) * D_];
                    float sim = s.c0;
#pragma unroll
                    for (int j = 0; j < D_; j++) sim += hrow[j] * s.va[j];
                    float e = expf_(sim - mx);
                    ssum += e;
#pragma unroll
                    for (int j = 0; j < D_; j++) acc[j] += e * hrow[j];
                }
                ssum = warp_sum_f(ssum);
#pragma unroll
                for (int j = 0; j < D_; j++) acc[j] = warp_sum_f(acc[j]);
                if (lane == 0) {
                    float inv = 1.0f / ssum;
#pragma unroll
                    for (int j = 0; j < D_; j++) s.beat_res[j] = acc[j] * inv;
                }
            }

            // ---- tempo LSTM gate partials (replicated; stream g_WtT global) ----
            {
                const int qg4 = t & 127;
                const int kh  = t >> 7;
                const ulonglong2* W4 = reinterpret_cast<const ulonglong2*>(g_WtT)
                                     + (size_t)kh * 32 * (GF_ / 4) + qg4;
                unsigned long long a01 = 0, a23 = 0;
#pragma unroll
                for (int k0 = 0; k0 < 32; ++k0) {
                    ulonglong2 w = __ldg(&W4[(size_t)k0 * (GF_ / 4)]);
                    unsigned long long hh = packf2(s.ht[kh * 32 + k0]);
                    ffma2(a01, w.x, hh);
                    ffma2(a23, w.y, hh);
                }
                float x0, x1, x2, x3;
                unpackf2(a01, x0, x1);
                unpackf2(a23, x2, x3);
                *reinterpret_cast<float4*>(&s.part[kh * GF_ + 4 * qg4]) =
                    make_float4(x0, x1, x2, x3);
            }
            __syncthreads();
            // ---- assemble tempo gates ----
            {
                float acc = s.part[t] + s.part[GF_ + t]
                          + s.part[2 * GF_ + t] + s.part[3 * GF_ + t]
                          + __ldg(&g_TBt[((size_t)b * NB_ + cb) * GF_ + t])
                          + __ldg(&g_TMt[((size_t)b * NM_ + cm) * GF_ + t]);
                acc += s.prev[0] * s.Wtt[t];
#pragma unroll
                for (int j = 0; j < D_; j++)
                    acc += s.beat_res[j] * s.Wtt[(1 + j) * GF_ + t];
                s.g[t] = acc;
            }
            __syncthreads();
            if (t < BH_) {
                float c2 = sigmoidf_(s.g[BH_ + t]) * s.ct[t]
                         + sigmoidf_(s.g[t]) * tanhf_(s.g[2 * BH_ + t]);
                float h2 = sigmoidf_(s.g[3 * BH_ + t]) * tanhf_(c2);
                s.ct[t] = c2;
                s.ht[t] = h2;
            }
            __syncthreads();
            if (wid == 0) {
                float p = s.ht[lane]      * s.Wtfc[lane]
                        + s.ht[lane + 32] * s.Wtfc[lane + 32]
                        + s.ht[lane + 64] * s.Wtfc[lane + 64]
                        + s.ht[lane + 96] * s.Wtfc[lane + 96];
                p = warp_sum_f(p);
                if (lane == 0) s.prev[0] = p + s.btfc;
            }
            rs = i;
        }

        // ---- final LSTM gate partials: all-SMEM weight stream ----
        {
            const int q  = t & 63;    // gate-quad (local gates 4q..4q+3)
            const int ks = t >> 6;    // k slice [16ks, 16ks+16)
            const float* hfb = s.hfbuf[rd];
            float hreg[16];
            {
                const float4* h4 = reinterpret_cast<const float4*>(hfb + ks * 16);
#pragma unroll
                for (int m = 0; m < 4; m++) {
                    float4 hv = h4[m];
                    hreg[4 * m + 0] = hv.x; hreg[4 * m + 1] = hv.y;
                    hreg[4 * m + 2] = hv.z; hreg[4 * m + 3] = hv.w;
                }
            }
            const ulonglong2* W2 = reinterpret_cast<const ulonglong2*>(s.wsm);
            unsigned long long a01 = 0, a23 = 0;
#pragma unroll
            for (int k0 = 0; k0 < 16; ++k0) {
                ulonglong2 w = W2[(16 * ks + k0) * 64 + q];
                unsigned long long hh = packf2(hreg[k0]);
                ffma2(a01, w.x, hh);
                ffma2(a23, w.y, hh);
            }
            float x0, x1, x2, x3;
            unpackf2(a01, x0, x1);
            unpackf2(a23, x2, x3);
            *reinterpret_cast<float4*>(&s.part[ks * 256 + 4 * q]) =
                make_float4(x0, x1, x2, x3);
        }
        __syncthreads();   // sync1

        // ---- cell update for this CTA's 64 units + exchange ----
        if (t < 64) {
            float gg[4];
#pragma unroll
            for (int g4 = 0; g4 < 4; g4++) {
                int l = g4 * 64 + t;
                float acc = in_g[g4];
#pragma unroll
                for (int ks = 0; ks < 8; ks++) acc += s.part[ks * 256 + l];
                int Gg = g4 * 128 + (int)rank * 64 + t;
#pragma unroll
                for (int j = 0; j < OUT_; j++) acc += s.prev[j] * s.Wtf[j * GF_ + Gg];
                gg[g4] = acc;
            }
            float c2 = sigmoidf_(gg[1]) * s.cfloc[t] + sigmoidf_(gg[0]) * tanhf_(gg[2]);
            float h2 = sigmoidf_(gg[3]) * tanhf_(c2);
            s.cfloc[t] = c2;
            int slot = (int)rank * 64 + t;
            s.hfbuf[wr][slot] = h2;
            uint32_t la = smem_u32(&s.hfbuf[wr][slot]);
            st_cluster_f32(mapa_peer(la, peer), h2);
            mbar_arrive_release_cluster(mbar_peer);   // release my DSMEM store
        }
        __syncthreads();   // sync2: local half + part consumption complete

        mbar_wait_parity_acq_cluster(mbar_local, ph); // peer half arrived (acquire)
        ph ^= 1;
    }

    // ---- epilogue: fc + write for step N-1 ----
    {
        const int j = N_ - 1;
        const int bidx = j & 1;
        if (wid < D_) {
            const float* hfb = s.hfbuf[bidx];
            float p = hfb[lane]      * s.Wfc[wid * FH_ + lane]
                    + hfb[lane + 32] * s.Wfc[wid * FH_ + lane + 32]
                    + hfb[lane + 64] * s.Wfc[wid * FH_ + lane + 64]
                    + hfb[lane + 96] * s.Wfc[wid * FH_ + lane + 96];
            p = warp_sum_f(p);
            if (lane == 0 && rank == 0) {
                float o = p + s.bfc[wid];
                bool pd = (g_pad[b * N_ + j] != 0);
                out[((size_t)b * N_ + j) * OUT_ + 1 + wid] = pd ? 0.f : o;
            }
        } else if (t == 320 && rank == 0) {
            bool pd = (g_pad[b * N_ + j] != 0);
            out[((size_t)b * N_ + j) * OUT_] = pd ? 0.f : s.prev[0];
        }
    }
    CLUSTER_SYNC_();   // no CTA exits while peer traffic may be in flight
}

// ---------------------------------------------------------------------------
// Launch  (6 launches; scan is the 6th so ncu -s 5 -c 1 profiles it)
// ---------------------------------------------------------------------------
extern "C" void kernel_launch(void* const* d_in, const int* in_sizes, int n_in,
                              void* d_out, int out_size) {
    const float* note_emb        = (const float*)d_in[0];
    const float* beat_emb        = (const float*)d_in[1];
    const float* measure_emb     = (const float*)d_in[2];
    const int*   beat_numbers    = (const int*)d_in[3];
    const int*   measure_numbers = (const int*)d_in[4];
    const float* Wa    = (const float*)d_in[5];
    const float* ba    = (const float*)d_in[6];
    const float* ctx   = (const float*)d_in[7];
    const float* Wih_t = (const float*)d_in[8];
    const float* Whh_t = (const float*)d_in[9];
    const float* bih_t = (const float*)d_in[10];
    const float* bhh_t = (const float*)d_in[11];
    const float* Wih_f = (const float*)d_in[12];
    const float* Whh_f = (const float*)d_in[13];
    const float* bih_f = (const float*)d_in[14];
    const float* bhh_f = (const float*)d_in[15];
    const float* W_fc  = (const float*)d_in[16];
    const float* b_fc  = (const float*)d_in[17];
    const float* W_tfc = (const float*)d_in[18];
    const float* b_tfc = (const float*)d_in[19];
    float* out = (float*)d_out;

    float *pG, *pTBf, *pTMf, *pTBt, *pTMt, *pWfT, *pWtT;
    unsigned char* pPad;
    cudaGetSymbolAddress((void**)&pG,   g_Gnote);
    cudaGetSymbolAddress((void**)&pTBf, g_TBf);
    cudaGetSymbolAddress((void**)&pTMf, g_TMf);
    cudaGetSymbolAddress((void**)&pTBt, g_TBt);
    cudaGetSymbolAddress((void**)&pTMt, g_TMt);
    cudaGetSymbolAddress((void**)&pWfT, g_WfT);
    cudaGetSymbolAddress((void**)&pWtT, g_WtT);
    cudaGetSymbolAddress((void**)&pPad, g_pad);

    cudaFuncSetAttribute(scan_kernel, cudaFuncAttributeMaxDynamicSharedMemorySize,
                         (int)sizeof(ScanSmem));

    // 1) both Whh transposes
    prep_kernel<<<512, 256>>>(Whh_f, pWfT, Whh_t, pWtT);
    // 2) pad mask
    pad_kernel<<<B_ * N_, 128>>>(note_emb, pPad);
    // 3) G_note = note_emb @ Wih_f[:, 0:512]^T      (32768 x 512 x 512)
    gemm_nt_kernel<<<dim3((B_ * N_) / GBM, GF_ / GBN), 256>>>(
        note_emb, NOTE_, NOTE_, Wih_f, LDF_, 0, pG, nullptr, nullptr);
    // 4) beat pair: TBf / TBt
    gemm_pair_kernel<<<dim3((B_ * NB_) / GBM, GF_ / GBN, 2), 256>>>(
        beat_emb, BH_, BH_,
        Wih_f, LDF_, NOTE_, pTBf, nullptr, nullptr,
        Wih_t, LDT_, 0,     pTBt, nullptr, nullptr);
    // 5) measure pair: TMf / TMt (with folded biases)
    gemm_pair_kernel<<<dim3((B_ * NM_) / GBM, GF_ / GBN, 2), 256>>>(
        measure_emb, MH_, MH_,
        Wih_f, LDF_, NOTE_ + BH_, pTMf, bih_f, bhh_f,
        Wih_t, LDT_, BH_,         pTMt, bih_t, bhh_t);
    // 6) scan
    scan_kernel<<<2 * B_, 512, sizeof(ScanSmem)>>>(
        beat_numbers, measure_numbers, Wa, ba, ctx,
        Wih_t, Wih_f, W_fc, b_fc, W_tfc, b_tfc, out);

    (void)in_sizes; (void)n_in; (void)out_size;
}